// round 14
// baseline (speedup 1.0000x reference)
#include <cuda_runtime.h>
#include <math.h>
#include <stdint.h>

#define Bb_ 16
#define T_ 500
#define D_ 768
#define FFN_ 3072
#define NH_ 12
#define DH_ 64
#define L_ 3

// ---------------- scratch (device globals; no allocation) ----------------
__device__ float g_bufA[49152000];   // conv ping
__device__ float g_bufB[24576000];   // conv pong / FFN hidden
__device__ float g_qer[48000000];    // qer buffer, head-major [h][b][q][r]
__device__ float g_qkv[18432000];    // fused QKV [8000][2304]
__device__ float g_wqkv[5308416];    // fused QKV weights [3][768][2304]
__device__ float g_bqkv[6912];       // fused QKV bias [3][2304]
__device__ float g_ert[32768];       // er transposed+scaled [64][512]
__device__ float g_zero[512];        // zero bias (device globals are zero-init)
__device__ float g_x[6144000];
__device__ float g_xn[6144000];
__device__ float g_o[6144000];

__device__ __forceinline__ float gelu_f(float x) {
    return 0.5f * x * (1.0f + erff(x * 0.7071067811865475f));
}

__device__ __forceinline__ uint32_t tf32_rn(float x) {
    uint32_t r; asm("cvt.rna.tf32.f32 %0, %1;" : "=r"(r) : "f"(x));
    return r;
}

__device__ __forceinline__ uint32_t smem_u32(const void* p) {
    uint32_t a;
    asm("{ .reg .u64 t; cvta.to.shared.u64 t, %1; cvt.u32.u64 %0, t; }" : "=r"(a) : "l"(p));
    return a;
}

// ---- packed f32x2 helpers (Blackwell FFMA2) ----
__device__ __forceinline__ unsigned long long pack_f32x2(float lo, float hi) {
    unsigned long long d;
    asm("mov.b64 %0, {%1, %2};" : "=l"(d) : "r"(__float_as_uint(lo)), "r"(__float_as_uint(hi)));
    return d;
}
__device__ __forceinline__ void unpack_f32x2(float& lo, float& hi, unsigned long long v) {
    uint32_t a, b;
    asm("mov.b64 {%0, %1}, %2;" : "=r"(a), "=r"(b) : "l"(v));
    lo = __uint_as_float(a); hi = __uint_as_float(b);
}
__device__ __forceinline__ void fma2(unsigned long long& d, unsigned long long a,
                                     unsigned long long b) {
    asm("fma.rn.f32x2 %0, %1, %2, %0;" : "+l"(d) : "l"(a), "l"(b));
}

// ---------------- tensor-core dense GEMM via mma.sync (tf32) ----------------
// CTA tile 128x128, K-step 32, double-buffered smem. 8 warps 4(m)x2(n).
#define ALD 136
#define STAGE_FLOATS (2 * 32 * ALD)
#define MM_SMEM_BYTES (2 * STAGE_FLOATS * 4)

extern __shared__ float mm_smem[];

__global__ void __launch_bounds__(256) mma_gemm_kernel(
    const float* __restrict__ A, const float* __restrict__ Bm,
    const float* __restrict__ bias, const float* __restrict__ addsrc,
    float* __restrict__ C, int M, int N, int K,
    int lda, int ldb, int ldc, int act, long long bAo, long long bCo)
{
    A += (long long)blockIdx.z * bAo;
    C += (long long)blockIdx.z * bCo;

    int tid = threadIdx.x;
    int wid = tid >> 5, lane = tid & 31;
    int grp = lane >> 2, tig = lane & 3;
    int wm = wid & 3, wn = wid >> 2;
    int m0 = blockIdx.y * 128, n0 = blockIdx.x * 128;

    int am = tid >> 1;
    int akh = (tid & 1) * 16;
    int bkr = tid >> 4;
    int bn = (tid & 15) * 8;

    float acc[2][8][4];
#pragma unroll
    for (int i = 0; i < 2; i++)
#pragma unroll
        for (int j = 0; j < 8; j++)
#pragma unroll
            for (int r = 0; r < 4; r++) acc[i][j][r] = 0.f;

    float4 pa[4], pb[2][2];
    bool okn = (n0 + bn < N);

    {
        const float* Ap = (m0 + am < M) ? A + (long long)(m0 + am) * lda + akh : (const float*)0;
#pragma unroll
        for (int i = 0; i < 4; i++)
            pa[i] = Ap ? *(const float4*)(Ap + i * 4) : make_float4(0.f, 0.f, 0.f, 0.f);
#pragma unroll
        for (int p = 0; p < 2; p++) {
            const float* Bp = Bm + (long long)(bkr + p * 16) * ldb + n0 + bn;
            pb[p][0] = okn ? *(const float4*)(Bp)     : make_float4(0.f, 0.f, 0.f, 0.f);
            pb[p][1] = okn ? *(const float4*)(Bp + 4) : make_float4(0.f, 0.f, 0.f, 0.f);
        }
    }
    {
        float* Asb = mm_smem;
        float* Bsb = mm_smem + 32 * ALD;
#pragma unroll
        for (int i = 0; i < 4; i++) {
            int kk = akh + i * 4;
            *(uint32_t*)&Asb[(kk + 0) * ALD + am] = tf32_rn(pa[i].x);
            *(uint32_t*)&Asb[(kk + 1) * ALD + am] = tf32_rn(pa[i].y);
            *(uint32_t*)&Asb[(kk + 2) * ALD + am] = tf32_rn(pa[i].z);
            *(uint32_t*)&Asb[(kk + 3) * ALD + am] = tf32_rn(pa[i].w);
        }
#pragma unroll
        for (int p = 0; p < 2; p++) {
            uint32_t* bsp = (uint32_t*)&Bsb[(bkr + p * 16) * ALD + bn];
            bsp[0] = tf32_rn(pb[p][0].x); bsp[1] = tf32_rn(pb[p][0].y);
            bsp[2] = tf32_rn(pb[p][0].z); bsp[3] = tf32_rn(pb[p][0].w);
            bsp[4] = tf32_rn(pb[p][1].x); bsp[5] = tf32_rn(pb[p][1].y);
            bsp[6] = tf32_rn(pb[p][1].z); bsp[7] = tf32_rn(pb[p][1].w);
        }
    }
    __syncthreads();

    int st = 0;
    for (int k0 = 0;; k0 += 32) {
        bool last = (k0 + 32 >= K);
        if (!last) {
            int kn = k0 + 32;
            const float* Ap = (m0 + am < M) ? A + (long long)(m0 + am) * lda + kn + akh : (const float*)0;
#pragma unroll
            for (int i = 0; i < 4; i++)
                pa[i] = Ap ? *(const float4*)(Ap + i * 4) : make_float4(0.f, 0.f, 0.f, 0.f);
#pragma unroll
            for (int p = 0; p < 2; p++) {
                const float* Bp = Bm + (long long)(kn + bkr + p * 16) * ldb + n0 + bn;
                pb[p][0] = okn ? *(const float4*)(Bp)     : make_float4(0.f, 0.f, 0.f, 0.f);
                pb[p][1] = okn ? *(const float4*)(Bp + 4) : make_float4(0.f, 0.f, 0.f, 0.f);
            }
        }

        {
            const float* Asb = mm_smem + st * STAGE_FLOATS;
            const float* Bsb = Asb + 32 * ALD;
#pragma unroll
            for (int ks = 0; ks < 4; ks++) {
                int kb = ks * 8;
                uint32_t a[2][4], b[8][2];
                int mB = wm * 32;
#pragma unroll
                for (int mf = 0; mf < 2; mf++) {
                    int mb = mB + mf * 16 + grp;
                    a[mf][0] = *(const uint32_t*)&Asb[(kb + tig) * ALD + mb];
                    a[mf][1] = *(const uint32_t*)&Asb[(kb + tig) * ALD + mb + 8];
                    a[mf][2] = *(const uint32_t*)&Asb[(kb + tig + 4) * ALD + mb];
                    a[mf][3] = *(const uint32_t*)&Asb[(kb + tig + 4) * ALD + mb + 8];
                }
                int nB = wn * 64;
#pragma unroll
                for (int nf = 0; nf < 8; nf++) {
                    int nb = nB + nf * 8 + grp;
                    b[nf][0] = *(const uint32_t*)&Bsb[(kb + tig) * ALD + nb];
                    b[nf][1] = *(const uint32_t*)&Bsb[(kb + tig + 4) * ALD + nb];
                }
#pragma unroll
                for (int mf = 0; mf < 2; mf++)
#pragma unroll
                    for (int nf = 0; nf < 8; nf++) {
                        asm volatile(
                            "mma.sync.aligned.m16n8k8.row.col.f32.tf32.tf32.f32 "
                            "{%0,%1,%2,%3}, {%4,%5,%6,%7}, {%8,%9}, {%0,%1,%2,%3};"
                            : "+f"(acc[mf][nf][0]), "+f"(acc[mf][nf][1]),
                              "+f"(acc[mf][nf][2]), "+f"(acc[mf][nf][3])
                            : "r"(a[mf][0]), "r"(a[mf][1]), "r"(a[mf][2]), "r"(a[mf][3]),
                              "r"(b[nf][0]), "r"(b[nf][1]));
                    }
            }
        }
        if (last) break;

        {
            float* Asb = mm_smem + (st ^ 1) * STAGE_FLOATS;
            float* Bsb = Asb + 32 * ALD;
#pragma unroll
            for (int i = 0; i < 4; i++) {
                int kk = akh + i * 4;
                *(uint32_t*)&Asb[(kk + 0) * ALD + am] = tf32_rn(pa[i].x);
                *(uint32_t*)&Asb[(kk + 1) * ALD + am] = tf32_rn(pa[i].y);
                *(uint32_t*)&Asb[(kk + 2) * ALD + am] = tf32_rn(pa[i].z);
                *(uint32_t*)&Asb[(kk + 3) * ALD + am] = tf32_rn(pa[i].w);
            }
#pragma unroll
            for (int p = 0; p < 2; p++) {
                uint32_t* bsp = (uint32_t*)&Bsb[(bkr + p * 16) * ALD + bn];
                bsp[0] = tf32_rn(pb[p][0].x); bsp[1] = tf32_rn(pb[p][0].y);
                bsp[2] = tf32_rn(pb[p][0].z); bsp[3] = tf32_rn(pb[p][0].w);
                bsp[4] = tf32_rn(pb[p][1].x); bsp[5] = tf32_rn(pb[p][1].y);
                bsp[6] = tf32_rn(pb[p][1].z); bsp[7] = tf32_rn(pb[p][1].w);
            }
        }
        __syncthreads();
        st ^= 1;
    }

#pragma unroll
    for (int mf = 0; mf < 2; mf++) {
#pragma unroll
        for (int r = 0; r < 2; r++) {
            int m = m0 + wm * 32 + mf * 16 + grp + r * 8;
            if (m >= M) continue;
            float* Cp = C + (long long)m * ldc;
            const float* addp = addsrc ? addsrc + (long long)m * ldc : (const float*)0;
#pragma unroll
            for (int nf = 0; nf < 8; nf++) {
                int n = n0 + wn * 64 + nf * 8 + tig * 2;
                if (n >= N) continue;
                float v0 = acc[mf][nf][r * 2 + 0] + bias[n];
                float v1 = acc[mf][nf][r * 2 + 1] + bias[n + 1];
                if (act) { v0 = gelu_f(v0); v1 = gelu_f(v1); }
                if (addp) { v0 += addp[n]; v1 += addp[n + 1]; }
                Cp[n] = v0; Cp[n + 1] = v1;
            }
        }
    }
}

// ---------------- 128x64-tile GEMM variant (N<=768 tail GEMMs) ----------------
// Validated R6 structure: single-stage smem + register prefetch, 8 warps 4(m)x2(n),
// warp tile 32x32. Requires K%32==0, N%8==0.
#define BLD64 72

__global__ void __launch_bounds__(256) mma_gemm_n64_kernel(
    const float* __restrict__ A, const float* __restrict__ Bm,
    const float* __restrict__ bias, const float* __restrict__ addsrc,
    float* __restrict__ C, int M, int N, int K,
    int lda, int ldb, int ldc, int act, long long bAo, long long bCo)
{
    __shared__ float As[32 * ALD];    // [k][m] 32 x 128 (+pad)
    __shared__ float Bs[32 * BLD64];  // [k][n] 32 x 64  (+pad)

    A += (long long)blockIdx.z * bAo;
    C += (long long)blockIdx.z * bCo;

    int tid = threadIdx.x;
    int wid = tid >> 5, lane = tid & 31;
    int grp = lane >> 2, tig = lane & 3;
    int wm = wid & 3, wn = wid >> 2;
    int m0 = blockIdx.y * 128, n0 = blockIdx.x * 64;

    int am = tid >> 1;
    int akh = (tid & 1) * 16;
    int bk = tid >> 3;               // 0..31
    int bn = (tid & 7) * 8;          // 0..56

    float acc[2][4][4];
#pragma unroll
    for (int i = 0; i < 2; i++)
#pragma unroll
        for (int j = 0; j < 4; j++)
#pragma unroll
            for (int r = 0; r < 4; r++) acc[i][j][r] = 0.f;

    float4 pa[4], pb[2];
    bool okn = (n0 + bn < N);
    {
        const float* Ap = (m0 + am < M) ? A + (long long)(m0 + am) * lda + akh : (const float*)0;
#pragma unroll
        for (int i = 0; i < 4; i++)
            pa[i] = Ap ? *(const float4*)(Ap + i * 4) : make_float4(0.f, 0.f, 0.f, 0.f);
        const float* Bp = Bm + (long long)bk * ldb + n0 + bn;
        pb[0] = okn ? *(const float4*)(Bp)     : make_float4(0.f, 0.f, 0.f, 0.f);
        pb[1] = okn ? *(const float4*)(Bp + 4) : make_float4(0.f, 0.f, 0.f, 0.f);
    }

    for (int k0 = 0;; k0 += 32) {
#pragma unroll
        for (int i = 0; i < 4; i++) {
            int kk = akh + i * 4;
            *(uint32_t*)&As[(kk + 0) * ALD + am] = tf32_rn(pa[i].x);
            *(uint32_t*)&As[(kk + 1) * ALD + am] = tf32_rn(pa[i].y);
            *(uint32_t*)&As[(kk + 2) * ALD + am] = tf32_rn(pa[i].z);
            *(uint32_t*)&As[(kk + 3) * ALD + am] = tf32_rn(pa[i].w);
        }
        {
            uint32_t* bsp = (uint32_t*)&Bs[bk * BLD64 + bn];
            bsp[0] = tf32_rn(pb[0].x); bsp[1] = tf32_rn(pb[0].y);
            bsp[2] = tf32_rn(pb[0].z); bsp[3] = tf32_rn(pb[0].w);
            bsp[4] = tf32_rn(pb[1].x); bsp[5] = tf32_rn(pb[1].y);
            bsp[6] = tf32_rn(pb[1].z); bsp[7] = tf32_rn(pb[1].w);
        }
        __syncthreads();

        bool last = (k0 + 32 >= K);
        if (!last) {
            int kn = k0 + 32;
            const float* Ap = (m0 + am < M) ? A + (long long)(m0 + am) * lda + kn + akh : (const float*)0;
#pragma unroll
            for (int i = 0; i < 4; i++)
                pa[i] = Ap ? *(const float4*)(Ap + i * 4) : make_float4(0.f, 0.f, 0.f, 0.f);
            const float* Bp = Bm + (long long)(kn + bk) * ldb + n0 + bn;
            pb[0] = okn ? *(const float4*)(Bp)     : make_float4(0.f, 0.f, 0.f, 0.f);
            pb[1] = okn ? *(const float4*)(Bp + 4) : make_float4(0.f, 0.f, 0.f, 0.f);
        }

#pragma unroll
        for (int ks = 0; ks < 4; ks++) {
            int kb = ks * 8;
            uint32_t a[2][4], b[4][2];
            int mB = wm * 32;
#pragma unroll
            for (int mf = 0; mf < 2; mf++) {
                int mb = mB + mf * 16 + grp;
                a[mf][0] = *(const uint32_t*)&As[(kb + tig) * ALD + mb];
                a[mf][1] = *(const uint32_t*)&As[(kb + tig) * ALD + mb + 8];
                a[mf][2] = *(const uint32_t*)&As[(kb + tig + 4) * ALD + mb];
                a[mf][3] = *(const uint32_t*)&As[(kb + tig + 4) * ALD + mb + 8];
            }
            int nB = wn * 32;
#pragma unroll
            for (int nf = 0; nf < 4; nf++) {
                int nb = nB + nf * 8 + grp;
                b[nf][0] = *(const uint32_t*)&Bs[(kb + tig) * BLD64 + nb];
                b[nf][1] = *(const uint32_t*)&Bs[(kb + tig + 4) * BLD64 + nb];
            }
#pragma unroll
            for (int mf = 0; mf < 2; mf++)
#pragma unroll
                for (int nf = 0; nf < 4; nf++) {
                    asm volatile(
                        "mma.sync.aligned.m16n8k8.row.col.f32.tf32.tf32.f32 "
                        "{%0,%1,%2,%3}, {%4,%5,%6,%7}, {%8,%9}, {%0,%1,%2,%3};"
                        : "+f"(acc[mf][nf][0]), "+f"(acc[mf][nf][1]),
                          "+f"(acc[mf][nf][2]), "+f"(acc[mf][nf][3])
                        : "r"(a[mf][0]), "r"(a[mf][1]), "r"(a[mf][2]), "r"(a[mf][3]),
                          "r"(b[nf][0]), "r"(b[nf][1]));
                }
        }
        if (last) break;
        __syncthreads();
    }

#pragma unroll
    for (int mf = 0; mf < 2; mf++) {
#pragma unroll
        for (int r = 0; r < 2; r++) {
            int m = m0 + wm * 32 + mf * 16 + grp + r * 8;
            if (m >= M) continue;
            float* Cp = C + (long long)m * ldc;
            const float* addp = addsrc ? addsrc + (long long)m * ldc : (const float*)0;
#pragma unroll
            for (int nf = 0; nf < 4; nf++) {
                int n = n0 + wn * 32 + nf * 8 + tig * 2;
                if (n >= N) continue;
                float v0 = acc[mf][nf][r * 2 + 0] + bias[n];
                float v1 = acc[mf][nf][r * 2 + 1] + bias[n + 1];
                if (act) { v0 = gelu_f(v0); v1 = gelu_f(v1); }
                if (addp) { v0 += addp[n]; v1 += addp[n + 1]; }
                Cp[n] = v0; Cp[n + 1] = v1;
            }
        }
    }
}

// ---------------- one-time weight prep kernels ----------------
__global__ void concat_qkv(const float* __restrict__ wq, const float* __restrict__ wk,
                           const float* __restrict__ wv, const float* __restrict__ bq,
                           const float* __restrict__ bk, const float* __restrict__ bv,
                           float* __restrict__ wqkv, float* __restrict__ bqkv)
{
    long long idx = (long long)blockIdx.x * blockDim.x + threadIdx.x;
    const long long TOT = 3LL * 768 * 2304;
    if (idx < TOT) {
        int i = (int)(idx / (768 * 2304));
        int rem = (int)(idx % (768 * 2304));
        int k = rem / 2304, n = rem % 2304;
        int sel = n / 768, nn = n % 768;
        const float* src = sel == 0 ? wq : sel == 1 ? wk : wv;
        wqkv[idx] = src[(long long)i * 589824 + k * 768 + nn];
    }
    if (idx < 3 * 2304) {
        int i = (int)(idx / 2304);
        int n = (int)(idx % 2304);
        int sel = n / 768, nn = n % 768;
        const float* src = sel == 0 ? bq : sel == 1 ? bk : bv;
        bqkv[idx] = src[i * 768 + nn];
    }
}

__global__ void er_transpose(const float* __restrict__ er, float* __restrict__ out)
{
    int d = blockIdx.x;
    int r = threadIdx.x;
    out[d * 512 + r] = (r < 500) ? 0.125f * er[r * 64 + d] : 0.f;
}

// ---------------- conv 5x5 + GELU + freq-maxpool, f32x2, cp.async pipelined ------
#define CTLD 76

__global__ void __launch_bounds__(128, 5) conv5x5_gelu_pool(
    const float* __restrict__ in, const float* __restrict__ w,
    const float* __restrict__ bias, float* __restrict__ out,
    int Ci, int Co, int H)
{
    const int W = 500;
    __shared__ float tile[2][28][CTLD];
    __shared__ float ws[6400];
    int tx = threadIdx.x, ty = threadIdx.y;
    int tid = ty * 32 + tx;
    int hBlocks = H / 24;
    int x0 = blockIdx.x * 64;
    int y0 = (blockIdx.y % hBlocks) * 24;
    int co0 = (blockIdx.y / hBlocks) * 4;
    int b = blockIdx.z;
    int HP = H >> 1;

    int wtot = 4 * Ci * 25;
    const float* wbase = w + (long long)co0 * Ci * 25;
    for (int s = tid; s < wtot; s += 128) ws[s] = wbase[s];

    uint32_t tb0 = smem_u32(&tile[0][0][0]);
    uint32_t tb1 = smem_u32(&tile[1][0][0]);

    auto issue = [&](int ci, int buf) {
        const float* ip = in + ((long long)(b * Ci + ci)) * H * W;
        uint32_t tb = buf ? tb1 : tb0;
        for (int idx = tid; idx < 448; idx += 128) {
            int r = idx >> 4, cv = idx & 15;
            int gy = y0 + r - 2;
            int gx = x0 + cv * 4;
            int sb = 0;
            if (gy >= 0 && gy < H) {
                int rem = W - gx;
                sb = rem >= 4 ? 16 : (rem > 0 ? rem * 4 : 0);
            }
            const float* src = (sb > 0) ? ip + (long long)gy * W + gx : ip;
            uint32_t dst = tb + (uint32_t)(r * CTLD + 4 + cv * 4) * 4u;
            asm volatile("cp.async.ca.shared.global [%0], [%1], 16, %2;"
                         :: "r"(dst), "l"(src), "r"(sb));
        }
        if (tid < 112) {
            int r = tid >> 2, hc = tid & 3;
            int col = (hc < 2) ? (2 + hc) : (66 + hc);
            int gx = (hc < 2) ? (x0 - 2 + hc) : (x0 + 62 + hc);
            int gy = y0 + r - 2;
            int sb = (gy >= 0 && gy < H && gx >= 0 && gx < W) ? 4 : 0;
            const float* src = sb ? ip + (long long)gy * W + gx : ip;
            uint32_t dst = tb + (uint32_t)(r * CTLD + col) * 4u;
            asm volatile("cp.async.ca.shared.global [%0], [%1], 4, %2;"
                         :: "r"(dst), "l"(src), "r"(sb));
        }
        asm volatile("cp.async.commit_group;" ::: "memory");
    };

    unsigned long long acc2[4][6];
#pragma unroll
    for (int i = 0; i < 4; i++)
#pragma unroll
        for (int j = 0; j < 6; j++) acc2[i][j] = 0ull;

    issue(0, 0);

    for (int ci = 0; ci < Ci; ci++) {
        asm volatile("cp.async.wait_group 0;" ::: "memory");
        __syncthreads();
        if (ci + 1 < Ci) issue(ci + 1, (ci + 1) & 1);

        const float (*tl)[CTLD] = tile[ci & 1];
#pragma unroll
        for (int dx = 0; dx < 5; dx++) {
            unsigned long long v2[10];
            if ((dx & 1) == 0) {
#pragma unroll
                for (int rr = 0; rr < 10; rr++)
                    v2[rr] = *(const unsigned long long*)&tl[ty * 6 + rr][2 * tx + dx + 2];
            } else {
#pragma unroll
                for (int rr = 0; rr < 10; rr++)
                    v2[rr] = pack_f32x2(tl[ty * 6 + rr][2 * tx + dx + 2],
                                        tl[ty * 6 + rr][2 * tx + dx + 3]);
            }
#pragma unroll
            for (int c4 = 0; c4 < 4; c4++) {
                const float* wp = ws + (c4 * Ci + ci) * 25 + dx;
#pragma unroll
                for (int dy = 0; dy < 5; dy++) {
                    float wv = wp[dy * 5];
                    unsigned long long w2 = pack_f32x2(wv, wv);
#pragma unroll
                    for (int ry = 0; ry < 6; ry++) fma2(acc2[c4][ry], v2[ry + dy], w2);
                }
            }
        }
    }

    int xe = x0 + 2 * tx;
#pragma unroll
    for (int c4 = 0; c4 < 4; c4++) {
        float bv = bias[co0 + c4];
#pragma unroll
        for (int p = 0; p < 3; p++) {
            int y = y0 + ty * 6 + 2 * p;
            float a0, a1, b0, b1;
            unpack_f32x2(a0, a1, acc2[c4][2 * p]);
            unpack_f32x2(b0, b1, acc2[c4][2 * p + 1]);
            float r0 = fmaxf(gelu_f(a0 + bv), gelu_f(b0 + bv));
            float r1 = fmaxf(gelu_f(a1 + bv), gelu_f(b1 + bv));
            long long base = (((long long)b * Co + co0 + c4) * HP + (y >> 1)) * W;
            if (xe < W)     out[base + xe]     = r0;
            if (xe + 1 < W) out[base + xe + 1] = r1;
        }
    }
}

// ---------------- transpose [B,768,500] -> [B,500,768] ----------------
__global__ void transpose_kernel(const float* __restrict__ in, float* __restrict__ out)
{
    __shared__ float t[32][33];
    int b = blockIdx.z;
    int k0 = blockIdx.x * 32;
    int t0 = blockIdx.y * 32;
    int tx = threadIdx.x, ty = threadIdx.y;
    const float* ip = in + (long long)b * 768 * 500;
    float* op = out + (long long)b * 500 * 768;
#pragma unroll
    for (int r = 0; r < 32; r += 8) {
        int kk = k0 + ty + r, tt = t0 + tx;
        t[ty + r][tx] = (tt < 500) ? ip[(long long)kk * 500 + tt] : 0.f;
    }
    __syncthreads();
#pragma unroll
    for (int r = 0; r < 32; r += 8) {
        int tt = t0 + ty + r, kk = k0 + tx;
        if (tt < 500) op[(long long)tt * 768 + kk] = t[tx][ty + r];
    }
}

// ---------------- flash attention (fused QK^T + skew + softmax + PV) ------------
#define FA_QLD 132
#define FA_KLD 68
#define FA_PLD 68
#define FA_SMEM_FLOATS (64*FA_QLD + 64*FA_KLD + 64*FA_KLD + 128*FA_PLD)

extern __shared__ float fa_smem[];

__global__ void __launch_bounds__(256) flash_attn_kernel(
    const float* __restrict__ Q, const float* __restrict__ K,
    const float* __restrict__ V, const float* __restrict__ qer,
    float* __restrict__ O, int ldin)
{
    float* Qs = fa_smem;
    float* Ks = Qs + 64 * FA_QLD;
    float* Vs = Ks + 64 * FA_KLD;
    float* Ps = Vs + 64 * FA_KLD;

    const float scale = 0.125f;
    int qt = blockIdx.x;
    int h = blockIdx.y, b = blockIdx.z;
    int q0 = qt * 128;
    const float* Qp = Q + (long long)b * 500 * ldin + h * 64;
    const float* Kp = K + (long long)b * 500 * ldin + h * 64;
    const float* Vp = V + (long long)b * 500 * ldin + h * 64;
    const float* qerp = qer + (long long)(h * 16 + b) * 250000;

    int tid = threadIdx.x;
    int tx = tid & 15, ty = tid >> 4;

#pragma unroll
    for (int i = 0; i < 8; i++) {
        int r = i * 16 + (tid >> 4);
        int d4 = (tid & 15) * 4;
        float4 v = make_float4(0.f, 0.f, 0.f, 0.f);
        if (q0 + r < 500) v = *(const float4*)(Qp + (long long)(q0 + r) * ldin + d4);
        Qs[(d4 + 0) * FA_QLD + r] = v.x;
        Qs[(d4 + 1) * FA_QLD + r] = v.y;
        Qs[(d4 + 2) * FA_QLD + r] = v.z;
        Qs[(d4 + 3) * FA_QLD + r] = v.w;
    }

    float m[8], l[8], o[8][4];
#pragma unroll
    for (int i = 0; i < 8; i++) {
        m[i] = -1e30f; l[i] = 0.f;
#pragma unroll
        for (int j = 0; j < 4; j++) o[i][j] = 0.f;
    }
    __syncthreads();

    for (int kt0 = 0; kt0 < 500; kt0 += 64) {
#pragma unroll
        for (int i = 0; i < 4; i++) {
            int r = i * 16 + (tid >> 4);
            int d4 = (tid & 15) * 4;
            float4 kv = make_float4(0.f, 0.f, 0.f, 0.f);
            float4 vv = make_float4(0.f, 0.f, 0.f, 0.f);
            if (kt0 + r < 500) {
                kv = *(const float4*)(Kp + (long long)(kt0 + r) * ldin + d4);
                vv = *(const float4*)(Vp + (long long)(kt0 + r) * ldin + d4);
            }
            Ks[(d4 + 0) * FA_KLD + r] = kv.x;
            Ks[(d4 + 1) * FA_KLD + r] = kv.y;
            Ks[(d4 + 2) * FA_KLD + r] = kv.z;
            Ks[(d4 + 3) * FA_KLD + r] = kv.w;
            *(float4*)(Vs + r * FA_KLD + d4) = vv;
        }
        __syncthreads();

        float S[8][4];
#pragma unroll
        for (int i = 0; i < 8; i++)
#pragma unroll
            for (int j = 0; j < 4; j++) S[i][j] = 0.f;
#pragma unroll
        for (int d = 0; d < 64; d++) {
            float a[8];
            *(float4*)&a[0] = *(const float4*)(Qs + d * FA_QLD + ty * 8);
            *(float4*)&a[4] = *(const float4*)(Qs + d * FA_QLD + ty * 8 + 4);
            float4 bb = *(const float4*)(Ks + d * FA_KLD + tx * 4);
#pragma unroll
            for (int i = 0; i < 8; i++) {
                S[i][0] += a[i] * bb.x; S[i][1] += a[i] * bb.y;
                S[i][2] += a[i] * bb.z; S[i][3] += a[i] * bb.w;
            }
        }
#pragma unroll
        for (int i = 0; i < 8; i++) {
            int q = q0 + ty * 8 + i;
#pragma unroll
            for (int j = 0; j < 4; j++) {
                int k = kt0 + tx * 4 + j;
                if (q < 500 && k < 500) {
                    float srel;
                    if (k <= q)          srel = qerp[(long long)q * 500 + 499 - q + k];
                    else if (k == q + 1) srel = 0.f;
                    else                 srel = qerp[(long long)(q + 1) * 500 + k - q - 2];
                    S[i][j] = S[i][j] * scale + srel;
                } else {
                    S[i][j] = -1e30f;
                }
            }
        }
#pragma unroll
        for (int i = 0; i < 8; i++) {
            float rmax = fmaxf(fmaxf(S[i][0], S[i][1]), fmaxf(S[i][2], S[i][3]));
#pragma unroll
            for (int off = 1; off < 16; off <<= 1)
                rmax = fmaxf(rmax, __shfl_xor_sync(0xffffffffu, rmax, off, 32));
            float mnew = fmaxf(m[i], rmax);
            float corr = __expf(m[i] - mnew);
            float rsum = 0.f;
#pragma unroll
            for (int j = 0; j < 4; j++) {
                S[i][j] = __expf(S[i][j] - mnew);
                rsum += S[i][j];
            }
#pragma unroll
            for (int off = 1; off < 16; off <<= 1)
                rsum += __shfl_xor_sync(0xffffffffu, rsum, off, 32);
            l[i] = l[i] * corr + rsum;
            m[i] = mnew;
#pragma unroll
            for (int j = 0; j < 4; j++) o[i][j] *= corr;
            *(float4*)(Ps + (long long)(ty * 8 + i) * FA_PLD + tx * 4) =
                make_float4(S[i][0], S[i][1], S[i][2], S[i][3]);
        }
        __syncthreads();

#pragma unroll
        for (int kk4 = 0; kk4 < 64; kk4 += 4) {
            float4 vr0 = *(const float4*)(Vs + (kk4 + 0) * FA_KLD + tx * 4);
            float4 vr1 = *(const float4*)(Vs + (kk4 + 1) * FA_KLD + tx * 4);
            float4 vr2 = *(const float4*)(Vs + (kk4 + 2) * FA_KLD + tx * 4);
            float4 vr3 = *(const float4*)(Vs + (kk4 + 3) * FA_KLD + tx * 4);
#pragma unroll
            for (int i = 0; i < 8; i++) {
                float4 p4 = *(const float4*)(Ps + (long long)(ty * 8 + i) * FA_PLD + kk4);
                o[i][0] += p4.x * vr0.x + p4.y * vr1.x + p4.z * vr2.x + p4.w * vr3.x;
                o[i][1] += p4.x * vr0.y + p4.y * vr1.y + p4.z * vr2.y + p4.w * vr3.y;
                o[i][2] += p4.x * vr0.z + p4.y * vr1.z + p4.z * vr2.z + p4.w * vr3.z;
                o[i][3] += p4.x * vr0.w + p4.y * vr1.w + p4.z * vr2.w + p4.w * vr3.w;
            }
        }
        __syncthreads();
    }

    float* Op = O + (long long)b * 500 * 768 + h * 64;
#pragma unroll
    for (int i = 0; i < 8; i++) {
        int q = q0 + ty * 8 + i;
        if (q < 500) {
            float inv = 1.0f / l[i];
            *(float4*)(Op + (long long)q * 768 + tx * 4) =
                make_float4(o[i][0] * inv, o[i][1] * inv, o[i][2] * inv, o[i][3] * inv);
        }
    }
}

// ---------------- layernorm (row = 768), warp-shuffle reductions ----------------
__global__ void __launch_bounds__(256) layernorm_kernel(
    const float* __restrict__ in, float* __restrict__ out,
    const float* __restrict__ g, const float* __restrict__ b)
{
    __shared__ float part[8];
    int row = blockIdx.x, tid = threadIdx.x;
    int wid = tid >> 5, lane = tid & 31;
    const float* xp = in + (long long)row * 768;
    float v0 = xp[tid], v1 = xp[tid + 256], v2 = xp[tid + 512];

    float s = v0 + v1 + v2;
#pragma unroll
    for (int off = 16; off > 0; off >>= 1) s += __shfl_xor_sync(0xffffffffu, s, off, 32);
    if (lane == 0) part[wid] = s;
    __syncthreads();
    float mean = (part[0] + part[1] + part[2] + part[3] +
                  part[4] + part[5] + part[6] + part[7]) * (1.0f / 768.0f);
    __syncthreads();

    float d0 = v0 - mean, d1 = v1 - mean, d2 = v2 - mean;
    float q = d0 * d0 + d1 * d1 + d2 * d2;
#pragma unroll
    for (int off = 16; off > 0; off >>= 1) q += __shfl_xor_sync(0xffffffffu, q, off, 32);
    if (lane == 0) part[wid] = q;
    __syncthreads();
    float var = (part[0] + part[1] + part[2] + part[3] +
                 part[4] + part[5] + part[6] + part[7]) * (1.0f / 768.0f);
    float rstd = rsqrtf(var + 1e-5f);

    float* op = out + (long long)row * 768;
    op[tid]       = d0 * rstd * g[tid]       + b[tid];
    op[tid + 256] = d1 * rstd * g[tid + 256] + b[tid + 256];
    op[tid + 512] = d2 * rstd * g[tid + 512] + b[tid + 512];
}

// ---------------- orchestration ----------------
static void tc(const float* A, const float* B, const float* bias, const float* add,
               float* C, int M, int N, int K, int lda, int ldb, int ldc, int act,
               int batch = 1, long long bAo = 0, long long bCo = 0)
{
    dim3 grid((N + 127) / 128, (M + 127) / 128, batch);
    mma_gemm_kernel<<<grid, 256, MM_SMEM_BYTES>>>(A, B, bias, add, C, M, N, K,
                                                  lda, ldb, ldc, act, bAo, bCo);
}

static void tc64(const float* A, const float* B, const float* bias, const float* add,
                 float* C, int M, int N, int K, int lda, int ldb, int ldc, int act)
{
    dim3 grid((N + 63) / 64, (M + 127) / 128, 1);
    mma_gemm_n64_kernel<<<grid, 256>>>(A, B, bias, add, C, M, N, K,
                                       lda, ldb, ldc, act, 0, 0);
}

extern "C" void kernel_launch(void* const* d_in, const int* in_sizes, int n_in,
                              void* d_out, int out_size)
{
    (void)in_sizes; (void)n_in; (void)out_size;
    const float* spec    = (const float*)d_in[0];
    const float* cw1     = (const float*)d_in[1];
    const float* cb1     = (const float*)d_in[2];
    const float* cw2     = (const float*)d_in[3];
    const float* cb2     = (const float*)d_in[4];
    const float* cw3     = (const float*)d_in[5];
    const float* cb3     = (const float*)d_in[6];
    const float* cw4     = (const float*)d_in[7];
    const float* cb4     = (const float*)d_in[8];
    const float* proj_w  = (const float*)d_in[9];
    const float* proj_b  = (const float*)d_in[10];
    const float* ln1_g   = (const float*)d_in[11];
    const float* ln1_b   = (const float*)d_in[12];
    const float* wq      = (const float*)d_in[13];
    const float* bq      = (const float*)d_in[14];
    const float* wk      = (const float*)d_in[15];
    const float* bk      = (const float*)d_in[16];
    const float* wv      = (const float*)d_in[17];
    const float* bv      = (const float*)d_in[18];
    const float* wo      = (const float*)d_in[19];
    const float* bo      = (const float*)d_in[20];
    const float* er      = (const float*)d_in[21];
    const float* ln2_g   = (const float*)d_in[22];
    const float* ln2_b   = (const float*)d_in[23];
    const float* w1      = (const float*)d_in[24];
    const float* b1      = (const float*)d_in[25];
    const float* w2      = (const float*)d_in[26];
    const float* b2      = (const float*)d_in[27];
    const float* deprj_w = (const float*)d_in[28];
    const float* deprj_b = (const float*)d_in[29];
    float* outp = (float*)d_out;

    float *bufA, *bufB, *qer, *qkv, *wqkv, *bqkv, *ert, *zerob, *x, *xn, *o;
    cudaGetSymbolAddress((void**)&bufA,  g_bufA);
    cudaGetSymbolAddress((void**)&bufB,  g_bufB);
    cudaGetSymbolAddress((void**)&qer,   g_qer);
    cudaGetSymbolAddress((void**)&qkv,   g_qkv);
    cudaGetSymbolAddress((void**)&wqkv,  g_wqkv);
    cudaGetSymbolAddress((void**)&bqkv,  g_bqkv);
    cudaGetSymbolAddress((void**)&ert,   g_ert);
    cudaGetSymbolAddress((void**)&zerob, g_zero);
    cudaGetSymbolAddress((void**)&x,     g_x);
    cudaGetSymbolAddress((void**)&xn,    g_xn);
    cudaGetSymbolAddress((void**)&o,     g_o);
    float* hbuf = bufB;

    const int fa_smem_bytes = FA_SMEM_FLOATS * 4;
    cudaFuncSetAttribute(flash_attn_kernel,
                         cudaFuncAttributeMaxDynamicSharedMemorySize, fa_smem_bytes);
    cudaFuncSetAttribute(mma_gemm_kernel,
                         cudaFuncAttributeMaxDynamicSharedMemorySize, MM_SMEM_BYTES);

    // --- one-time QKV weight/bias concat ---
    concat_qkv<<<(3 * 768 * 2304 + 255) / 256, 256>>>(wq, wk, wv, bq, bk, bv, wqkv, bqkv);

    dim3 cblk(32, 4);
    // --- CNN with fused GELU+maxpool ---
    conv5x5_gelu_pool<<<dim3(8, 8 * 8, 16), cblk>>>(spec, cw1, cb1, bufB, 1, 32, 192);
    conv5x5_gelu_pool<<<dim3(8, 4 * 16, 16), cblk>>>(bufB, cw2, cb2, bufA, 32, 64, 96);
    conv5x5_gelu_pool<<<dim3(8, 2 * 16, 16), cblk>>>(bufA, cw3, cb3, bufB, 64, 64, 48);
    conv5x5_gelu_pool<<<dim3(8, 1 * 16, 16), cblk>>>(bufB, cw4, cb4, bufA, 64, 64, 24);
    transpose_kernel<<<dim3(24, 16, 16), dim3(32, 8)>>>(bufA, xn);

    // proj (N=768 -> n64 variant)
    tc64(xn, proj_w, proj_b, 0, x, 8000, 768, 768, 768, 768, 768, 0);

    for (int i = 0; i < L_; i++) {
        layernorm_kernel<<<8000, 256>>>(x, xn, ln1_g + i * 768, ln1_b + i * 768);
        // fused QKV: [8000][2304] (wide N -> 128 tile)
        tc(xn, wqkv + (long long)i * 768 * 2304, bqkv + i * 2304, 0, qkv,
           8000, 2304, 768, 768, 2304, 2304, 0);
        // er transposed+scaled -> [64][512]
        er_transpose<<<64, 512>>>(er + (long long)i * 500 * 64, ert);
        // qer (head-major) = Q_h @ er^T, batched over 12 heads
        tc(qkv, ert, zerob, 0, qer, 8000, 500, 64, 2304, 512, 500, 0,
           12, 64LL, 4000000LL);
        // fused attention
        flash_attn_kernel<<<dim3(4, 12, 16), 256, fa_smem_bytes>>>(
            qkv, qkv + 768, qkv + 1536, qer, o, 2304);
        // x = x + o @ wo + bo  (N=768 -> n64)
        tc64(o, wo + (long long)i * 768 * 768, bo + i * 768, x, x, 8000, 768, 768, 768, 768, 768, 0);
        layernorm_kernel<<<8000, 256>>>(x, xn, ln2_g + i * 768, ln2_b + i * 768);
        // h = gelu(xn @ w1 + b1)  (wide N -> 128 tile)
        tc(xn, w1 + (long long)i * 768 * 3072, b1 + i * 3072, 0, hbuf, 8000, 3072, 768,
           768, 3072, 3072, 1);
        // x = x + h @ w2 + b2  (N=768 -> n64)
        tc64(hbuf, w2 + (long long)i * 3072 * 768, b2 + i * 768, x, x, 8000, 768, 3072,
             3072, 768, 768, 0);
    }
    // final deproj (N=192 -> n64)
    tc64(x, deprj_w, deprj_b, 0, outp, 8000, 192, 768, 768, 192, 192, 0);
}

// round 15
// speedup vs baseline: 1.0595x; 1.0595x over previous
#include <cuda_runtime.h>
#include <math.h>
#include <stdint.h>

#define Bb_ 16
#define T_ 500
#define D_ 768
#define FFN_ 3072
#define NH_ 12
#define DH_ 64
#define L_ 3

// ---------------- scratch (device globals; no allocation) ----------------
__device__ float g_bufA[49152000];   // conv ping
__device__ float g_bufB[24576000];   // conv pong / FFN hidden
__device__ float g_qer[48000000];    // qer buffer, head-major [h][b][q][r]
__device__ float g_qkv[18432000];    // fused QKV [8000][2304]
__device__ float g_wqkv[5308416];    // fused QKV weights [3][768][2304]
__device__ float g_bqkv[6912];       // fused QKV bias [3][2304]
__device__ float g_ert[98304];       // er transposed+scaled [3][64][512]
__device__ float g_zero[512];        // zero bias (device globals are zero-init)
__device__ float g_x[6144000];
__device__ float g_xn[6144000];
__device__ float g_o[6144000];

__device__ __forceinline__ float gelu_f(float x) {
    return 0.5f * x * (1.0f + erff(x * 0.7071067811865475f));
}

__device__ __forceinline__ uint32_t tf32_rn(float x) {
    uint32_t r; asm("cvt.rna.tf32.f32 %0, %1;" : "=r"(r) : "f"(x));
    return r;
}

__device__ __forceinline__ uint32_t smem_u32(const void* p) {
    uint32_t a;
    asm("{ .reg .u64 t; cvta.to.shared.u64 t, %1; cvt.u32.u64 %0, t; }" : "=r"(a) : "l"(p));
    return a;
}

// ---- packed f32x2 helpers (Blackwell FFMA2) ----
__device__ __forceinline__ unsigned long long pack_f32x2(float lo, float hi) {
    unsigned long long d;
    asm("mov.b64 %0, {%1, %2};" : "=l"(d) : "r"(__float_as_uint(lo)), "r"(__float_as_uint(hi)));
    return d;
}
__device__ __forceinline__ void unpack_f32x2(float& lo, float& hi, unsigned long long v) {
    uint32_t a, b;
    asm("mov.b64 {%0, %1}, %2;" : "=r"(a), "=r"(b) : "l"(v));
    lo = __uint_as_float(a); hi = __uint_as_float(b);
}
__device__ __forceinline__ void fma2(unsigned long long& d, unsigned long long a,
                                     unsigned long long b) {
    asm("fma.rn.f32x2 %0, %1, %2, %0;" : "+l"(d) : "l"(a), "l"(b));
}

// ---------------- tensor-core dense GEMM via mma.sync (tf32) ----------------
// CTA tile 128x128, K-step 32, double-buffered smem. 8 warps 4(m)x2(n).
#define ALD 136
#define STAGE_FLOATS (2 * 32 * ALD)
#define MM_SMEM_BYTES (2 * STAGE_FLOATS * 4)

extern __shared__ float mm_smem[];

__global__ void __launch_bounds__(256) mma_gemm_kernel(
    const float* __restrict__ A, const float* __restrict__ Bm,
    const float* __restrict__ bias, const float* __restrict__ addsrc,
    float* __restrict__ C, int M, int N, int K,
    int lda, int ldb, int ldc, int act, long long bAo, long long bCo)
{
    A += (long long)blockIdx.z * bAo;
    C += (long long)blockIdx.z * bCo;

    int tid = threadIdx.x;
    int wid = tid >> 5, lane = tid & 31;
    int grp = lane >> 2, tig = lane & 3;
    int wm = wid & 3, wn = wid >> 2;
    int m0 = blockIdx.y * 128, n0 = blockIdx.x * 128;

    int am = tid >> 1;
    int akh = (tid & 1) * 16;
    int bkr = tid >> 4;
    int bn = (tid & 15) * 8;

    float acc[2][8][4];
#pragma unroll
    for (int i = 0; i < 2; i++)
#pragma unroll
        for (int j = 0; j < 8; j++)
#pragma unroll
            for (int r = 0; r < 4; r++) acc[i][j][r] = 0.f;

    float4 pa[4], pb[2][2];
    bool okn = (n0 + bn < N);

    {
        const float* Ap = (m0 + am < M) ? A + (long long)(m0 + am) * lda + akh : (const float*)0;
#pragma unroll
        for (int i = 0; i < 4; i++)
            pa[i] = Ap ? *(const float4*)(Ap + i * 4) : make_float4(0.f, 0.f, 0.f, 0.f);
#pragma unroll
        for (int p = 0; p < 2; p++) {
            const float* Bp = Bm + (long long)(bkr + p * 16) * ldb + n0 + bn;
            pb[p][0] = okn ? *(const float4*)(Bp)     : make_float4(0.f, 0.f, 0.f, 0.f);
            pb[p][1] = okn ? *(const float4*)(Bp + 4) : make_float4(0.f, 0.f, 0.f, 0.f);
        }
    }
    {
        float* Asb = mm_smem;
        float* Bsb = mm_smem + 32 * ALD;
#pragma unroll
        for (int i = 0; i < 4; i++) {
            int kk = akh + i * 4;
            *(uint32_t*)&Asb[(kk + 0) * ALD + am] = tf32_rn(pa[i].x);
            *(uint32_t*)&Asb[(kk + 1) * ALD + am] = tf32_rn(pa[i].y);
            *(uint32_t*)&Asb[(kk + 2) * ALD + am] = tf32_rn(pa[i].z);
            *(uint32_t*)&Asb[(kk + 3) * ALD + am] = tf32_rn(pa[i].w);
        }
#pragma unroll
        for (int p = 0; p < 2; p++) {
            uint32_t* bsp = (uint32_t*)&Bsb[(bkr + p * 16) * ALD + bn];
            bsp[0] = tf32_rn(pb[p][0].x); bsp[1] = tf32_rn(pb[p][0].y);
            bsp[2] = tf32_rn(pb[p][0].z); bsp[3] = tf32_rn(pb[p][0].w);
            bsp[4] = tf32_rn(pb[p][1].x); bsp[5] = tf32_rn(pb[p][1].y);
            bsp[6] = tf32_rn(pb[p][1].z); bsp[7] = tf32_rn(pb[p][1].w);
        }
    }
    __syncthreads();

    int st = 0;
    for (int k0 = 0;; k0 += 32) {
        bool last = (k0 + 32 >= K);
        if (!last) {
            int kn = k0 + 32;
            const float* Ap = (m0 + am < M) ? A + (long long)(m0 + am) * lda + kn + akh : (const float*)0;
#pragma unroll
            for (int i = 0; i < 4; i++)
                pa[i] = Ap ? *(const float4*)(Ap + i * 4) : make_float4(0.f, 0.f, 0.f, 0.f);
#pragma unroll
            for (int p = 0; p < 2; p++) {
                const float* Bp = Bm + (long long)(kn + bkr + p * 16) * ldb + n0 + bn;
                pb[p][0] = okn ? *(const float4*)(Bp)     : make_float4(0.f, 0.f, 0.f, 0.f);
                pb[p][1] = okn ? *(const float4*)(Bp + 4) : make_float4(0.f, 0.f, 0.f, 0.f);
            }
        }

        {
            const float* Asb = mm_smem + st * STAGE_FLOATS;
            const float* Bsb = Asb + 32 * ALD;
#pragma unroll
            for (int ks = 0; ks < 4; ks++) {
                int kb = ks * 8;
                uint32_t a[2][4], b[8][2];
                int mB = wm * 32;
#pragma unroll
                for (int mf = 0; mf < 2; mf++) {
                    int mb = mB + mf * 16 + grp;
                    a[mf][0] = *(const uint32_t*)&Asb[(kb + tig) * ALD + mb];
                    a[mf][1] = *(const uint32_t*)&Asb[(kb + tig) * ALD + mb + 8];
                    a[mf][2] = *(const uint32_t*)&Asb[(kb + tig + 4) * ALD + mb];
                    a[mf][3] = *(const uint32_t*)&Asb[(kb + tig + 4) * ALD + mb + 8];
                }
                int nB = wn * 64;
#pragma unroll
                for (int nf = 0; nf < 8; nf++) {
                    int nb = nB + nf * 8 + grp;
                    b[nf][0] = *(const uint32_t*)&Bsb[(kb + tig) * ALD + nb];
                    b[nf][1] = *(const uint32_t*)&Bsb[(kb + tig + 4) * ALD + nb];
                }
#pragma unroll
                for (int mf = 0; mf < 2; mf++)
#pragma unroll
                    for (int nf = 0; nf < 8; nf++) {
                        asm volatile(
                            "mma.sync.aligned.m16n8k8.row.col.f32.tf32.tf32.f32 "
                            "{%0,%1,%2,%3}, {%4,%5,%6,%7}, {%8,%9}, {%0,%1,%2,%3};"
                            : "+f"(acc[mf][nf][0]), "+f"(acc[mf][nf][1]),
                              "+f"(acc[mf][nf][2]), "+f"(acc[mf][nf][3])
                            : "r"(a[mf][0]), "r"(a[mf][1]), "r"(a[mf][2]), "r"(a[mf][3]),
                              "r"(b[nf][0]), "r"(b[nf][1]));
                    }
            }
        }
        if (last) break;

        {
            float* Asb = mm_smem + (st ^ 1) * STAGE_FLOATS;
            float* Bsb = Asb + 32 * ALD;
#pragma unroll
            for (int i = 0; i < 4; i++) {
                int kk = akh + i * 4;
                *(uint32_t*)&Asb[(kk + 0) * ALD + am] = tf32_rn(pa[i].x);
                *(uint32_t*)&Asb[(kk + 1) * ALD + am] = tf32_rn(pa[i].y);
                *(uint32_t*)&Asb[(kk + 2) * ALD + am] = tf32_rn(pa[i].z);
                *(uint32_t*)&Asb[(kk + 3) * ALD + am] = tf32_rn(pa[i].w);
            }
#pragma unroll
            for (int p = 0; p < 2; p++) {
                uint32_t* bsp = (uint32_t*)&Bsb[(bkr + p * 16) * ALD + bn];
                bsp[0] = tf32_rn(pb[p][0].x); bsp[1] = tf32_rn(pb[p][0].y);
                bsp[2] = tf32_rn(pb[p][0].z); bsp[3] = tf32_rn(pb[p][0].w);
                bsp[4] = tf32_rn(pb[p][1].x); bsp[5] = tf32_rn(pb[p][1].y);
                bsp[6] = tf32_rn(pb[p][1].z); bsp[7] = tf32_rn(pb[p][1].w);
            }
        }
        __syncthreads();
        st ^= 1;
    }

#pragma unroll
    for (int mf = 0; mf < 2; mf++) {
#pragma unroll
        for (int r = 0; r < 2; r++) {
            int m = m0 + wm * 32 + mf * 16 + grp + r * 8;
            if (m >= M) continue;
            float* Cp = C + (long long)m * ldc;
            const float* addp = addsrc ? addsrc + (long long)m * ldc : (const float*)0;
#pragma unroll
            for (int nf = 0; nf < 8; nf++) {
                int n = n0 + wn * 64 + nf * 8 + tig * 2;
                if (n >= N) continue;
                float v0 = acc[mf][nf][r * 2 + 0] + bias[n];
                float v1 = acc[mf][nf][r * 2 + 1] + bias[n + 1];
                if (act) { v0 = gelu_f(v0); v1 = gelu_f(v1); }
                if (addp) { v0 += addp[n]; v1 += addp[n + 1]; }
                Cp[n] = v0; Cp[n + 1] = v1;
            }
        }
    }
}

// ---------------- one-time weight prep kernels ----------------
__global__ void concat_qkv(const float* __restrict__ wq, const float* __restrict__ wk,
                           const float* __restrict__ wv, const float* __restrict__ bq,
                           const float* __restrict__ bk, const float* __restrict__ bv,
                           float* __restrict__ wqkv, float* __restrict__ bqkv)
{
    long long idx = (long long)blockIdx.x * blockDim.x + threadIdx.x;
    const long long TOT = 3LL * 768 * 2304;
    if (idx < TOT) {
        int i = (int)(idx / (768 * 2304));
        int rem = (int)(idx % (768 * 2304));
        int k = rem / 2304, n = rem % 2304;
        int sel = n / 768, nn = n % 768;
        const float* src = sel == 0 ? wq : sel == 1 ? wk : wv;
        wqkv[idx] = src[(long long)i * 589824 + k * 768 + nn];
    }
    if (idx < 3 * 2304) {
        int i = (int)(idx / 2304);
        int n = (int)(idx % 2304);
        int sel = n / 768, nn = n % 768;
        const float* src = sel == 0 ? bq : sel == 1 ? bk : bv;
        bqkv[idx] = src[i * 768 + nn];
    }
}

// er [L][500][64] -> out [L][64][512]: out[l][d][r] = 0.125*er[l][r][d], zero-padded
__global__ void er_transpose_all(const float* __restrict__ er, float* __restrict__ out)
{
    int l = blockIdx.y;
    int d = blockIdx.x;
    int r = threadIdx.x;
    out[(l * 64 + d) * 512 + r] =
        (r < 500) ? 0.125f * er[(long long)l * 32000 + r * 64 + d] : 0.f;
}

// ---------------- conv 5x5 + GELU + freq-maxpool, f32x2, cp.async pipelined ------
#define CTLD 76

__global__ void __launch_bounds__(128, 5) conv5x5_gelu_pool(
    const float* __restrict__ in, const float* __restrict__ w,
    const float* __restrict__ bias, float* __restrict__ out,
    int Ci, int Co, int H)
{
    const int W = 500;
    __shared__ float tile[2][28][CTLD];
    __shared__ float ws[6400];
    int tx = threadIdx.x, ty = threadIdx.y;
    int tid = ty * 32 + tx;
    int hBlocks = H / 24;
    int x0 = blockIdx.x * 64;
    int y0 = (blockIdx.y % hBlocks) * 24;
    int co0 = (blockIdx.y / hBlocks) * 4;
    int b = blockIdx.z;
    int HP = H >> 1;

    int wtot = 4 * Ci * 25;
    const float* wbase = w + (long long)co0 * Ci * 25;
    for (int s = tid; s < wtot; s += 128) ws[s] = wbase[s];

    uint32_t tb0 = smem_u32(&tile[0][0][0]);
    uint32_t tb1 = smem_u32(&tile[1][0][0]);

    auto issue = [&](int ci, int buf) {
        const float* ip = in + ((long long)(b * Ci + ci)) * H * W;
        uint32_t tb = buf ? tb1 : tb0;
        for (int idx = tid; idx < 448; idx += 128) {
            int r = idx >> 4, cv = idx & 15;
            int gy = y0 + r - 2;
            int gx = x0 + cv * 4;
            int sb = 0;
            if (gy >= 0 && gy < H) {
                int rem = W - gx;
                sb = rem >= 4 ? 16 : (rem > 0 ? rem * 4 : 0);
            }
            const float* src = (sb > 0) ? ip + (long long)gy * W + gx : ip;
            uint32_t dst = tb + (uint32_t)(r * CTLD + 4 + cv * 4) * 4u;
            asm volatile("cp.async.ca.shared.global [%0], [%1], 16, %2;"
                         :: "r"(dst), "l"(src), "r"(sb));
        }
        if (tid < 112) {
            int r = tid >> 2, hc = tid & 3;
            int col = (hc < 2) ? (2 + hc) : (66 + hc);
            int gx = (hc < 2) ? (x0 - 2 + hc) : (x0 + 62 + hc);
            int gy = y0 + r - 2;
            int sb = (gy >= 0 && gy < H && gx >= 0 && gx < W) ? 4 : 0;
            const float* src = sb ? ip + (long long)gy * W + gx : ip;
            uint32_t dst = tb + (uint32_t)(r * CTLD + col) * 4u;
            asm volatile("cp.async.ca.shared.global [%0], [%1], 4, %2;"
                         :: "r"(dst), "l"(src), "r"(sb));
        }
        asm volatile("cp.async.commit_group;" ::: "memory");
    };

    unsigned long long acc2[4][6];
#pragma unroll
    for (int i = 0; i < 4; i++)
#pragma unroll
        for (int j = 0; j < 6; j++) acc2[i][j] = 0ull;

    issue(0, 0);

    for (int ci = 0; ci < Ci; ci++) {
        asm volatile("cp.async.wait_group 0;" ::: "memory");
        __syncthreads();
        if (ci + 1 < Ci) issue(ci + 1, (ci + 1) & 1);

        const float (*tl)[CTLD] = tile[ci & 1];
#pragma unroll
        for (int dx = 0; dx < 5; dx++) {
            unsigned long long v2[10];
            if ((dx & 1) == 0) {
#pragma unroll
                for (int rr = 0; rr < 10; rr++)
                    v2[rr] = *(const unsigned long long*)&tl[ty * 6 + rr][2 * tx + dx + 2];
            } else {
#pragma unroll
                for (int rr = 0; rr < 10; rr++)
                    v2[rr] = pack_f32x2(tl[ty * 6 + rr][2 * tx + dx + 2],
                                        tl[ty * 6 + rr][2 * tx + dx + 3]);
            }
#pragma unroll
            for (int c4 = 0; c4 < 4; c4++) {
                const float* wp = ws + (c4 * Ci + ci) * 25 + dx;
#pragma unroll
                for (int dy = 0; dy < 5; dy++) {
                    float wv = wp[dy * 5];
                    unsigned long long w2 = pack_f32x2(wv, wv);
#pragma unroll
                    for (int ry = 0; ry < 6; ry++) fma2(acc2[c4][ry], v2[ry + dy], w2);
                }
            }
        }
    }

    int xe = x0 + 2 * tx;
#pragma unroll
    for (int c4 = 0; c4 < 4; c4++) {
        float bv = bias[co0 + c4];
#pragma unroll
        for (int p = 0; p < 3; p++) {
            int y = y0 + ty * 6 + 2 * p;
            float a0, a1, b0, b1;
            unpack_f32x2(a0, a1, acc2[c4][2 * p]);
            unpack_f32x2(b0, b1, acc2[c4][2 * p + 1]);
            float r0 = fmaxf(gelu_f(a0 + bv), gelu_f(b0 + bv));
            float r1 = fmaxf(gelu_f(a1 + bv), gelu_f(b1 + bv));
            long long base = (((long long)b * Co + co0 + c4) * HP + (y >> 1)) * W;
            if (xe < W)     out[base + xe]     = r0;
            if (xe + 1 < W) out[base + xe + 1] = r1;
        }
    }
}

// ---------------- transpose [B,768,500] -> [B,500,768] ----------------
__global__ void transpose_kernel(const float* __restrict__ in, float* __restrict__ out)
{
    __shared__ float t[32][33];
    int b = blockIdx.z;
    int k0 = blockIdx.x * 32;
    int t0 = blockIdx.y * 32;
    int tx = threadIdx.x, ty = threadIdx.y;
    const float* ip = in + (long long)b * 768 * 500;
    float* op = out + (long long)b * 500 * 768;
#pragma unroll
    for (int r = 0; r < 32; r += 8) {
        int kk = k0 + ty + r, tt = t0 + tx;
        t[ty + r][tx] = (tt < 500) ? ip[(long long)kk * 500 + tt] : 0.f;
    }
    __syncthreads();
#pragma unroll
    for (int r = 0; r < 32; r += 8) {
        int tt = t0 + ty + r, kk = k0 + tx;
        if (tt < 500) op[(long long)tt * 768 + kk] = t[tx][ty + r];
    }
}

// ---------------- flash attention (fused QK^T + skew + softmax + PV) ------------
#define FA_QLD 132
#define FA_KLD 68
#define FA_PLD 68
#define FA_SMEM_FLOATS (64*FA_QLD + 64*FA_KLD + 64*FA_KLD + 128*FA_PLD)

extern __shared__ float fa_smem[];

__global__ void __launch_bounds__(256) flash_attn_kernel(
    const float* __restrict__ Q, const float* __restrict__ K,
    const float* __restrict__ V, const float* __restrict__ qer,
    float* __restrict__ O, int ldin)
{
    float* Qs = fa_smem;
    float* Ks = Qs + 64 * FA_QLD;
    float* Vs = Ks + 64 * FA_KLD;
    float* Ps = Vs + 64 * FA_KLD;

    const float scale = 0.125f;
    int qt = blockIdx.x;
    int h = blockIdx.y, b = blockIdx.z;
    int q0 = qt * 128;
    const float* Qp = Q + (long long)b * 500 * ldin + h * 64;
    const float* Kp = K + (long long)b * 500 * ldin + h * 64;
    const float* Vp = V + (long long)b * 500 * ldin + h * 64;
    const float* qerp = qer + (long long)(h * 16 + b) * 250000;

    int tid = threadIdx.x;
    int tx = tid & 15, ty = tid >> 4;

#pragma unroll
    for (int i = 0; i < 8; i++) {
        int r = i * 16 + (tid >> 4);
        int d4 = (tid & 15) * 4;
        float4 v = make_float4(0.f, 0.f, 0.f, 0.f);
        if (q0 + r < 500) v = *(const float4*)(Qp + (long long)(q0 + r) * ldin + d4);
        Qs[(d4 + 0) * FA_QLD + r] = v.x;
        Qs[(d4 + 1) * FA_QLD + r] = v.y;
        Qs[(d4 + 2) * FA_QLD + r] = v.z;
        Qs[(d4 + 3) * FA_QLD + r] = v.w;
    }

    float m[8], l[8], o[8][4];
#pragma unroll
    for (int i = 0; i < 8; i++) {
        m[i] = -1e30f; l[i] = 0.f;
#pragma unroll
        for (int j = 0; j < 4; j++) o[i][j] = 0.f;
    }
    __syncthreads();

    for (int kt0 = 0; kt0 < 500; kt0 += 64) {
#pragma unroll
        for (int i = 0; i < 4; i++) {
            int r = i * 16 + (tid >> 4);
            int d4 = (tid & 15) * 4;
            float4 kv = make_float4(0.f, 0.f, 0.f, 0.f);
            float4 vv = make_float4(0.f, 0.f, 0.f, 0.f);
            if (kt0 + r < 500) {
                kv = *(const float4*)(Kp + (long long)(kt0 + r) * ldin + d4);
                vv = *(const float4*)(Vp + (long long)(kt0 + r) * ldin + d4);
            }
            Ks[(d4 + 0) * FA_KLD + r] = kv.x;
            Ks[(d4 + 1) * FA_KLD + r] = kv.y;
            Ks[(d4 + 2) * FA_KLD + r] = kv.z;
            Ks[(d4 + 3) * FA_KLD + r] = kv.w;
            *(float4*)(Vs + r * FA_KLD + d4) = vv;
        }
        __syncthreads();

        float S[8][4];
#pragma unroll
        for (int i = 0; i < 8; i++)
#pragma unroll
            for (int j = 0; j < 4; j++) S[i][j] = 0.f;
#pragma unroll
        for (int d = 0; d < 64; d++) {
            float a[8];
            *(float4*)&a[0] = *(const float4*)(Qs + d * FA_QLD + ty * 8);
            *(float4*)&a[4] = *(const float4*)(Qs + d * FA_QLD + ty * 8 + 4);
            float4 bb = *(const float4*)(Ks + d * FA_KLD + tx * 4);
#pragma unroll
            for (int i = 0; i < 8; i++) {
                S[i][0] += a[i] * bb.x; S[i][1] += a[i] * bb.y;
                S[i][2] += a[i] * bb.z; S[i][3] += a[i] * bb.w;
            }
        }
#pragma unroll
        for (int i = 0; i < 8; i++) {
            int q = q0 + ty * 8 + i;
#pragma unroll
            for (int j = 0; j < 4; j++) {
                int k = kt0 + tx * 4 + j;
                if (q < 500 && k < 500) {
                    float srel;
                    if (k <= q)          srel = qerp[(long long)q * 500 + 499 - q + k];
                    else if (k == q + 1) srel = 0.f;
                    else                 srel = qerp[(long long)(q + 1) * 500 + k - q - 2];
                    S[i][j] = S[i][j] * scale + srel;
                } else {
                    S[i][j] = -1e30f;
                }
            }
        }
#pragma unroll
        for (int i = 0; i < 8; i++) {
            float rmax = fmaxf(fmaxf(S[i][0], S[i][1]), fmaxf(S[i][2], S[i][3]));
#pragma unroll
            for (int off = 1; off < 16; off <<= 1)
                rmax = fmaxf(rmax, __shfl_xor_sync(0xffffffffu, rmax, off, 32));
            float mnew = fmaxf(m[i], rmax);
            float corr = __expf(m[i] - mnew);
            float rsum = 0.f;
#pragma unroll
            for (int j = 0; j < 4; j++) {
                S[i][j] = __expf(S[i][j] - mnew);
                rsum += S[i][j];
            }
#pragma unroll
            for (int off = 1; off < 16; off <<= 1)
                rsum += __shfl_xor_sync(0xffffffffu, rsum, off, 32);
            l[i] = l[i] * corr + rsum;
            m[i] = mnew;
#pragma unroll
            for (int j = 0; j < 4; j++) o[i][j] *= corr;
            *(float4*)(Ps + (long long)(ty * 8 + i) * FA_PLD + tx * 4) =
                make_float4(S[i][0], S[i][1], S[i][2], S[i][3]);
        }
        __syncthreads();

#pragma unroll
        for (int kk4 = 0; kk4 < 64; kk4 += 4) {
            float4 vr0 = *(const float4*)(Vs + (kk4 + 0) * FA_KLD + tx * 4);
            float4 vr1 = *(const float4*)(Vs + (kk4 + 1) * FA_KLD + tx * 4);
            float4 vr2 = *(const float4*)(Vs + (kk4 + 2) * FA_KLD + tx * 4);
            float4 vr3 = *(const float4*)(Vs + (kk4 + 3) * FA_KLD + tx * 4);
#pragma unroll
            for (int i = 0; i < 8; i++) {
                float4 p4 = *(const float4*)(Ps + (long long)(ty * 8 + i) * FA_PLD + kk4);
                o[i][0] += p4.x * vr0.x + p4.y * vr1.x + p4.z * vr2.x + p4.w * vr3.x;
                o[i][1] += p4.x * vr0.y + p4.y * vr1.y + p4.z * vr2.y + p4.w * vr3.y;
                o[i][2] += p4.x * vr0.z + p4.y * vr1.z + p4.z * vr2.z + p4.w * vr3.z;
                o[i][3] += p4.x * vr0.w + p4.y * vr1.w + p4.z * vr2.w + p4.w * vr3.w;
            }
        }
        __syncthreads();
    }

    float* Op = O + (long long)b * 500 * 768 + h * 64;
#pragma unroll
    for (int i = 0; i < 8; i++) {
        int q = q0 + ty * 8 + i;
        if (q < 500) {
            float inv = 1.0f / l[i];
            *(float4*)(Op + (long long)q * 768 + tx * 4) =
                make_float4(o[i][0] * inv, o[i][1] * inv, o[i][2] * inv, o[i][3] * inv);
        }
    }
}

// ---------------- layernorm (row = 768), warp-shuffle reductions ----------------
__global__ void __launch_bounds__(256) layernorm_kernel(
    const float* __restrict__ in, float* __restrict__ out,
    const float* __restrict__ g, const float* __restrict__ b)
{
    __shared__ float part[8];
    int row = blockIdx.x, tid = threadIdx.x;
    int wid = tid >> 5, lane = tid & 31;
    const float* xp = in + (long long)row * 768;
    float v0 = xp[tid], v1 = xp[tid + 256], v2 = xp[tid + 512];

    float s = v0 + v1 + v2;
#pragma unroll
    for (int off = 16; off > 0; off >>= 1) s += __shfl_xor_sync(0xffffffffu, s, off, 32);
    if (lane == 0) part[wid] = s;
    __syncthreads();
    float mean = (part[0] + part[1] + part[2] + part[3] +
                  part[4] + part[5] + part[6] + part[7]) * (1.0f / 768.0f);
    __syncthreads();

    float d0 = v0 - mean, d1 = v1 - mean, d2 = v2 - mean;
    float q = d0 * d0 + d1 * d1 + d2 * d2;
#pragma unroll
    for (int off = 16; off > 0; off >>= 1) q += __shfl_xor_sync(0xffffffffu, q, off, 32);
    if (lane == 0) part[wid] = q;
    __syncthreads();
    float var = (part[0] + part[1] + part[2] + part[3] +
                 part[4] + part[5] + part[6] + part[7]) * (1.0f / 768.0f);
    float rstd = rsqrtf(var + 1e-5f);

    float* op = out + (long long)row * 768;
    op[tid]       = d0 * rstd * g[tid]       + b[tid];
    op[tid + 256] = d1 * rstd * g[tid + 256] + b[tid + 256];
    op[tid + 512] = d2 * rstd * g[tid + 512] + b[tid + 512];
}

// ---------------- orchestration ----------------
static void tc(const float* A, const float* B, const float* bias, const float* add,
               float* C, int M, int N, int K, int lda, int ldb, int ldc, int act,
               int batch = 1, long long bAo = 0, long long bCo = 0)
{
    dim3 grid((N + 127) / 128, (M + 127) / 128, batch);
    mma_gemm_kernel<<<grid, 256, MM_SMEM_BYTES>>>(A, B, bias, add, C, M, N, K,
                                                  lda, ldb, ldc, act, bAo, bCo);
}

extern "C" void kernel_launch(void* const* d_in, const int* in_sizes, int n_in,
                              void* d_out, int out_size)
{
    (void)in_sizes; (void)n_in; (void)out_size;
    const float* spec    = (const float*)d_in[0];
    const float* cw1     = (const float*)d_in[1];
    const float* cb1     = (const float*)d_in[2];
    const float* cw2     = (const float*)d_in[3];
    const float* cb2     = (const float*)d_in[4];
    const float* cw3     = (const float*)d_in[5];
    const float* cb3     = (const float*)d_in[6];
    const float* cw4     = (const float*)d_in[7];
    const float* cb4     = (const float*)d_in[8];
    const float* proj_w  = (const float*)d_in[9];
    const float* proj_b  = (const float*)d_in[10];
    const float* ln1_g   = (const float*)d_in[11];
    const float* ln1_b   = (const float*)d_in[12];
    const float* wq      = (const float*)d_in[13];
    const float* bq      = (const float*)d_in[14];
    const float* wk      = (const float*)d_in[15];
    const float* bk      = (const float*)d_in[16];
    const float* wv      = (const float*)d_in[17];
    const float* bv      = (const float*)d_in[18];
    const float* wo      = (const float*)d_in[19];
    const float* bo      = (const float*)d_in[20];
    const float* er      = (const float*)d_in[21];
    const float* ln2_g   = (const float*)d_in[22];
    const float* ln2_b   = (const float*)d_in[23];
    const float* w1      = (const float*)d_in[24];
    const float* b1      = (const float*)d_in[25];
    const float* w2      = (const float*)d_in[26];
    const float* b2      = (const float*)d_in[27];
    const float* deprj_w = (const float*)d_in[28];
    const float* deprj_b = (const float*)d_in[29];
    float* outp = (float*)d_out;

    float *bufA, *bufB, *qer, *qkv, *wqkv, *bqkv, *ert, *zerob, *x, *xn, *o;
    cudaGetSymbolAddress((void**)&bufA,  g_bufA);
    cudaGetSymbolAddress((void**)&bufB,  g_bufB);
    cudaGetSymbolAddress((void**)&qer,   g_qer);
    cudaGetSymbolAddress((void**)&qkv,   g_qkv);
    cudaGetSymbolAddress((void**)&wqkv,  g_wqkv);
    cudaGetSymbolAddress((void**)&bqkv,  g_bqkv);
    cudaGetSymbolAddress((void**)&ert,   g_ert);
    cudaGetSymbolAddress((void**)&zerob, g_zero);
    cudaGetSymbolAddress((void**)&x,     g_x);
    cudaGetSymbolAddress((void**)&xn,    g_xn);
    cudaGetSymbolAddress((void**)&o,     g_o);
    float* hbuf = bufB;

    const int fa_smem_bytes = FA_SMEM_FLOATS * 4;
    cudaFuncSetAttribute(flash_attn_kernel,
                         cudaFuncAttributeMaxDynamicSharedMemorySize, fa_smem_bytes);
    cudaFuncSetAttribute(mma_gemm_kernel,
                         cudaFuncAttributeMaxDynamicSharedMemorySize, MM_SMEM_BYTES);

    // --- one-time prep: QKV weight/bias concat + er transpose (all layers) ---
    concat_qkv<<<(3 * 768 * 2304 + 255) / 256, 256>>>(wq, wk, wv, bq, bk, bv, wqkv, bqkv);
    er_transpose_all<<<dim3(64, 3), 512>>>(er, ert);

    dim3 cblk(32, 4);
    // --- CNN with fused GELU+maxpool ---
    conv5x5_gelu_pool<<<dim3(8, 8 * 8, 16), cblk>>>(spec, cw1, cb1, bufB, 1, 32, 192);
    conv5x5_gelu_pool<<<dim3(8, 4 * 16, 16), cblk>>>(bufB, cw2, cb2, bufA, 32, 64, 96);
    conv5x5_gelu_pool<<<dim3(8, 2 * 16, 16), cblk>>>(bufA, cw3, cb3, bufB, 64, 64, 48);
    conv5x5_gelu_pool<<<dim3(8, 1 * 16, 16), cblk>>>(bufB, cw4, cb4, bufA, 64, 64, 24);
    transpose_kernel<<<dim3(24, 16, 16), dim3(32, 8)>>>(bufA, xn);

    // proj
    tc(xn, proj_w, proj_b, 0, x, 8000, 768, 768, 768, 768, 768, 0);

    for (int i = 0; i < L_; i++) {
        layernorm_kernel<<<8000, 256>>>(x, xn, ln1_g + i * 768, ln1_b + i * 768);
        // fused QKV: [8000][2304]
        tc(xn, wqkv + (long long)i * 768 * 2304, bqkv + i * 2304, 0, qkv,
           8000, 2304, 768, 768, 2304, 2304, 0);
        // qer (head-major) = Q_h @ er^T, batched over 12 heads
        tc(qkv, ert + (long long)i * 32768, zerob, 0, qer, 8000, 500, 64, 2304, 512, 500, 0,
           12, 64LL, 4000000LL);
        // fused attention
        flash_attn_kernel<<<dim3(4, 12, 16), 256, fa_smem_bytes>>>(
            qkv, qkv + 768, qkv + 1536, qer, o, 2304);
        // x = x + o @ wo + bo
        tc(o, wo + (long long)i * 768 * 768, bo + i * 768, x, x, 8000, 768, 768, 768, 768, 768, 0);
        layernorm_kernel<<<8000, 256>>>(x, xn, ln2_g + i * 768, ln2_b + i * 768);
        // h = gelu(xn @ w1 + b1)
        tc(xn, w1 + (long long)i * 768 * 3072, b1 + i * 3072, 0, hbuf, 8000, 3072, 768,
           768, 3072, 3072, 1);
        // x = x + h @ w2 + b2
        tc(hbuf, w2 + (long long)i * 3072 * 768, b2 + i * 768, x, x, 8000, 768, 3072,
           3072, 768, 768, 0);
    }
    // final deproj
    tc(x, deprj_w, deprj_b, 0, outp, 8000, 192, 768, 768, 192, 192, 0);
}

// round 16
// speedup vs baseline: 1.0675x; 1.0075x over previous
#include <cuda_runtime.h>
#include <math.h>
#include <stdint.h>

#define Bb_ 16
#define T_ 500
#define D_ 768
#define FFN_ 3072
#define NH_ 12
#define DH_ 64
#define L_ 3

// ---------------- scratch (device globals; no allocation) ----------------
__device__ float g_bufA[49152000];   // conv ping
__device__ float g_bufB[24576000];   // conv pong / FFN hidden
__device__ float g_qer[48000000];    // qer buffer, head-major [h][b][q][r]
__device__ float g_qkv[18432000];    // fused QKV [8000][2304]
__device__ float g_wqkv[5308416];    // fused QKV weights [3][768][2304]
__device__ float g_bqkv[6912];       // fused QKV bias [3][2304]
__device__ float g_ert[98304];       // er transposed+scaled [3][64][512]
__device__ float g_zero[512];        // zero bias (device globals are zero-init)
__device__ float g_x[6144000];
__device__ float g_xn[6144000];
__device__ float g_o[6144000];

__device__ __forceinline__ float gelu_f(float x) {
    return 0.5f * x * (1.0f + erff(x * 0.7071067811865475f));
}

__device__ __forceinline__ uint32_t tf32_rn(float x) {
    uint32_t r; asm("cvt.rna.tf32.f32 %0, %1;" : "=r"(r) : "f"(x));
    return r;
}

__device__ __forceinline__ uint32_t smem_u32(const void* p) {
    uint32_t a;
    asm("{ .reg .u64 t; cvta.to.shared.u64 t, %1; cvt.u32.u64 %0, t; }" : "=r"(a) : "l"(p));
    return a;
}

// ---- packed f32x2 helpers (Blackwell FFMA2) ----
__device__ __forceinline__ unsigned long long pack_f32x2(float lo, float hi) {
    unsigned long long d;
    asm("mov.b64 %0, {%1, %2};" : "=l"(d) : "r"(__float_as_uint(lo)), "r"(__float_as_uint(hi)));
    return d;
}
__device__ __forceinline__ void unpack_f32x2(float& lo, float& hi, unsigned long long v) {
    uint32_t a, b;
    asm("mov.b64 {%0, %1}, %2;" : "=r"(a), "=r"(b) : "l"(v));
    lo = __uint_as_float(a); hi = __uint_as_float(b);
}
__device__ __forceinline__ void fma2(unsigned long long& d, unsigned long long a,
                                     unsigned long long b) {
    asm("fma.rn.f32x2 %0, %1, %2, %0;" : "+l"(d) : "l"(a), "l"(b));
}

// ---------------- tensor-core dense GEMM via mma.sync (tf32) ----------------
// CTA tile 128x128, K-step 32, double-buffered smem. 8 warps 4(m)x2(n).
// A staged [m][k] ld=36 (vector STS.128); B staged [k][n] ld=136.
#define ALD 136
#define AKLD 36
#define A_STG (128 * AKLD)                 // 4608 floats
#define STAGE_FLOATS (A_STG + 32 * ALD)    // 4608 + 4352 = 8960
#define MM_SMEM_BYTES (2 * STAGE_FLOATS * 4)

extern __shared__ float mm_smem[];

__global__ void __launch_bounds__(256) mma_gemm_kernel(
    const float* __restrict__ A, const float* __restrict__ Bm,
    const float* __restrict__ bias, const float* __restrict__ addsrc,
    float* __restrict__ C, int M, int N, int K,
    int lda, int ldb, int ldc, int act, long long bAo, long long bCo)
{
    A += (long long)blockIdx.z * bAo;
    C += (long long)blockIdx.z * bCo;

    int tid = threadIdx.x;
    int wid = tid >> 5, lane = tid & 31;
    int grp = lane >> 2, tig = lane & 3;
    int wm = wid & 3, wn = wid >> 2;
    int m0 = blockIdx.y * 128, n0 = blockIdx.x * 128;

    int am = tid >> 1;
    int akh = (tid & 1) * 16;
    int bkr = tid >> 4;
    int bn = (tid & 15) * 8;

    float acc[2][8][4];
#pragma unroll
    for (int i = 0; i < 2; i++)
#pragma unroll
        for (int j = 0; j < 8; j++)
#pragma unroll
            for (int r = 0; r < 4; r++) acc[i][j][r] = 0.f;

    float4 pa[4], pb[2][2];
    bool okn = (n0 + bn < N);

    // staging helper (vectorized STS.128)
    auto stage = [&](float* Asb, float* Bsb) {
#pragma unroll
        for (int i = 0; i < 4; i++) {
            uint4 q;
            q.x = tf32_rn(pa[i].x); q.y = tf32_rn(pa[i].y);
            q.z = tf32_rn(pa[i].z); q.w = tf32_rn(pa[i].w);
            *(uint4*)&Asb[am * AKLD + akh + i * 4] = q;
        }
#pragma unroll
        for (int p = 0; p < 2; p++) {
            uint4 q0, q1;
            q0.x = tf32_rn(pb[p][0].x); q0.y = tf32_rn(pb[p][0].y);
            q0.z = tf32_rn(pb[p][0].z); q0.w = tf32_rn(pb[p][0].w);
            q1.x = tf32_rn(pb[p][1].x); q1.y = tf32_rn(pb[p][1].y);
            q1.z = tf32_rn(pb[p][1].z); q1.w = tf32_rn(pb[p][1].w);
            uint32_t* bsp = (uint32_t*)&Bsb[(bkr + p * 16) * ALD + bn];
            *(uint4*)(bsp) = q0;
            *(uint4*)(bsp + 4) = q1;
        }
    };

    // prologue load k-tile 0
    {
        const float* Ap = (m0 + am < M) ? A + (long long)(m0 + am) * lda + akh : (const float*)0;
#pragma unroll
        for (int i = 0; i < 4; i++)
            pa[i] = Ap ? *(const float4*)(Ap + i * 4) : make_float4(0.f, 0.f, 0.f, 0.f);
#pragma unroll
        for (int p = 0; p < 2; p++) {
            const float* Bp = Bm + (long long)(bkr + p * 16) * ldb + n0 + bn;
            pb[p][0] = okn ? *(const float4*)(Bp)     : make_float4(0.f, 0.f, 0.f, 0.f);
            pb[p][1] = okn ? *(const float4*)(Bp + 4) : make_float4(0.f, 0.f, 0.f, 0.f);
        }
    }
    stage(mm_smem, mm_smem + A_STG);
    __syncthreads();

    int st = 0;
    for (int k0 = 0;; k0 += 32) {
        bool last = (k0 + 32 >= K);
        if (!last) {
            int kn = k0 + 32;
            const float* Ap = (m0 + am < M) ? A + (long long)(m0 + am) * lda + kn + akh : (const float*)0;
#pragma unroll
            for (int i = 0; i < 4; i++)
                pa[i] = Ap ? *(const float4*)(Ap + i * 4) : make_float4(0.f, 0.f, 0.f, 0.f);
#pragma unroll
            for (int p = 0; p < 2; p++) {
                const float* Bp = Bm + (long long)(kn + bkr + p * 16) * ldb + n0 + bn;
                pb[p][0] = okn ? *(const float4*)(Bp)     : make_float4(0.f, 0.f, 0.f, 0.f);
                pb[p][1] = okn ? *(const float4*)(Bp + 4) : make_float4(0.f, 0.f, 0.f, 0.f);
            }
        }

        {
            const float* Asb = mm_smem + st * STAGE_FLOATS;
            const float* Bsb = Asb + A_STG;
#pragma unroll
            for (int ks = 0; ks < 4; ks++) {
                int kb = ks * 8;
                uint32_t a[2][4], b[8][2];
                int mB = wm * 32;
#pragma unroll
                for (int mf = 0; mf < 2; mf++) {
                    int mb = mB + mf * 16 + grp;
                    a[mf][0] = *(const uint32_t*)&Asb[(mb)     * AKLD + kb + tig];
                    a[mf][1] = *(const uint32_t*)&Asb[(mb + 8) * AKLD + kb + tig];
                    a[mf][2] = *(const uint32_t*)&Asb[(mb)     * AKLD + kb + tig + 4];
                    a[mf][3] = *(const uint32_t*)&Asb[(mb + 8) * AKLD + kb + tig + 4];
                }
                int nB = wn * 64;
#pragma unroll
                for (int nf = 0; nf < 8; nf++) {
                    int nb = nB + nf * 8 + grp;
                    b[nf][0] = *(const uint32_t*)&Bsb[(kb + tig) * ALD + nb];
                    b[nf][1] = *(const uint32_t*)&Bsb[(kb + tig + 4) * ALD + nb];
                }
#pragma unroll
                for (int mf = 0; mf < 2; mf++)
#pragma unroll
                    for (int nf = 0; nf < 8; nf++) {
                        asm volatile(
                            "mma.sync.aligned.m16n8k8.row.col.f32.tf32.tf32.f32 "
                            "{%0,%1,%2,%3}, {%4,%5,%6,%7}, {%8,%9}, {%0,%1,%2,%3};"
                            : "+f"(acc[mf][nf][0]), "+f"(acc[mf][nf][1]),
                              "+f"(acc[mf][nf][2]), "+f"(acc[mf][nf][3])
                            : "r"(a[mf][0]), "r"(a[mf][1]), "r"(a[mf][2]), "r"(a[mf][3]),
                              "r"(b[nf][0]), "r"(b[nf][1]));
                    }
            }
        }
        if (last) break;

        stage(mm_smem + (st ^ 1) * STAGE_FLOATS,
              mm_smem + (st ^ 1) * STAGE_FLOATS + A_STG);
        __syncthreads();
        st ^= 1;
    }

#pragma unroll
    for (int mf = 0; mf < 2; mf++) {
#pragma unroll
        for (int r = 0; r < 2; r++) {
            int m = m0 + wm * 32 + mf * 16 + grp + r * 8;
            if (m >= M) continue;
            float* Cp = C + (long long)m * ldc;
            const float* addp = addsrc ? addsrc + (long long)m * ldc : (const float*)0;
#pragma unroll
            for (int nf = 0; nf < 8; nf++) {
                int n = n0 + wn * 64 + nf * 8 + tig * 2;
                if (n >= N) continue;
                float v0 = acc[mf][nf][r * 2 + 0] + bias[n];
                float v1 = acc[mf][nf][r * 2 + 1] + bias[n + 1];
                if (act) { v0 = gelu_f(v0); v1 = gelu_f(v1); }
                if (addp) { v0 += addp[n]; v1 += addp[n + 1]; }
                Cp[n] = v0; Cp[n + 1] = v1;
            }
        }
    }
}

// ---------------- one-time weight prep kernels ----------------
__global__ void concat_qkv(const float* __restrict__ wq, const float* __restrict__ wk,
                           const float* __restrict__ wv, const float* __restrict__ bq,
                           const float* __restrict__ bk, const float* __restrict__ bv,
                           float* __restrict__ wqkv, float* __restrict__ bqkv)
{
    long long idx = (long long)blockIdx.x * blockDim.x + threadIdx.x;
    const long long TOT = 3LL * 768 * 2304;
    if (idx < TOT) {
        int i = (int)(idx / (768 * 2304));
        int rem = (int)(idx % (768 * 2304));
        int k = rem / 2304, n = rem % 2304;
        int sel = n / 768, nn = n % 768;
        const float* src = sel == 0 ? wq : sel == 1 ? wk : wv;
        wqkv[idx] = src[(long long)i * 589824 + k * 768 + nn];
    }
    if (idx < 3 * 2304) {
        int i = (int)(idx / 2304);
        int n = (int)(idx % 2304);
        int sel = n / 768, nn = n % 768;
        const float* src = sel == 0 ? bq : sel == 1 ? bk : bv;
        bqkv[idx] = src[i * 768 + nn];
    }
}

// er [L][500][64] -> out [L][64][512]: out[l][d][r] = 0.125*er[l][r][d], zero-padded
__global__ void er_transpose_all(const float* __restrict__ er, float* __restrict__ out)
{
    int l = blockIdx.y;
    int d = blockIdx.x;
    int r = threadIdx.x;
    out[(l * 64 + d) * 512 + r] =
        (r < 500) ? 0.125f * er[(long long)l * 32000 + r * 64 + d] : 0.f;
}

// ---------------- conv 5x5 + GELU + freq-maxpool, f32x2, cp.async pipelined ------
#define CTLD 76

__global__ void __launch_bounds__(128, 5) conv5x5_gelu_pool(
    const float* __restrict__ in, const float* __restrict__ w,
    const float* __restrict__ bias, float* __restrict__ out,
    int Ci, int Co, int H)
{
    const int W = 500;
    __shared__ float tile[2][28][CTLD];
    __shared__ float ws[6400];
    int tx = threadIdx.x, ty = threadIdx.y;
    int tid = ty * 32 + tx;
    int hBlocks = H / 24;
    int x0 = blockIdx.x * 64;
    int y0 = (blockIdx.y % hBlocks) * 24;
    int co0 = (blockIdx.y / hBlocks) * 4;
    int b = blockIdx.z;
    int HP = H >> 1;

    int wtot = 4 * Ci * 25;
    const float* wbase = w + (long long)co0 * Ci * 25;
    for (int s = tid; s < wtot; s += 128) ws[s] = wbase[s];

    uint32_t tb0 = smem_u32(&tile[0][0][0]);
    uint32_t tb1 = smem_u32(&tile[1][0][0]);

    auto issue = [&](int ci, int buf) {
        const float* ip = in + ((long long)(b * Ci + ci)) * H * W;
        uint32_t tb = buf ? tb1 : tb0;
        for (int idx = tid; idx < 448; idx += 128) {
            int r = idx >> 4, cv = idx & 15;
            int gy = y0 + r - 2;
            int gx = x0 + cv * 4;
            int sb = 0;
            if (gy >= 0 && gy < H) {
                int rem = W - gx;
                sb = rem >= 4 ? 16 : (rem > 0 ? rem * 4 : 0);
            }
            const float* src = (sb > 0) ? ip + (long long)gy * W + gx : ip;
            uint32_t dst = tb + (uint32_t)(r * CTLD + 4 + cv * 4) * 4u;
            asm volatile("cp.async.ca.shared.global [%0], [%1], 16, %2;"
                         :: "r"(dst), "l"(src), "r"(sb));
        }
        if (tid < 112) {
            int r = tid >> 2, hc = tid & 3;
            int col = (hc < 2) ? (2 + hc) : (66 + hc);
            int gx = (hc < 2) ? (x0 - 2 + hc) : (x0 + 62 + hc);
            int gy = y0 + r - 2;
            int sb = (gy >= 0 && gy < H && gx >= 0 && gx < W) ? 4 : 0;
            const float* src = sb ? ip + (long long)gy * W + gx : ip;
            uint32_t dst = tb + (uint32_t)(r * CTLD + col) * 4u;
            asm volatile("cp.async.ca.shared.global [%0], [%1], 4, %2;"
                         :: "r"(dst), "l"(src), "r"(sb));
        }
        asm volatile("cp.async.commit_group;" ::: "memory");
    };

    unsigned long long acc2[4][6];
#pragma unroll
    for (int i = 0; i < 4; i++)
#pragma unroll
        for (int j = 0; j < 6; j++) acc2[i][j] = 0ull;

    issue(0, 0);

    for (int ci = 0; ci < Ci; ci++) {
        asm volatile("cp.async.wait_group 0;" ::: "memory");
        __syncthreads();
        if (ci + 1 < Ci) issue(ci + 1, (ci + 1) & 1);

        const float (*tl)[CTLD] = tile[ci & 1];
#pragma unroll
        for (int dx = 0; dx < 5; dx++) {
            unsigned long long v2[10];
            if ((dx & 1) == 0) {
#pragma unroll
                for (int rr = 0; rr < 10; rr++)
                    v2[rr] = *(const unsigned long long*)&tl[ty * 6 + rr][2 * tx + dx + 2];
            } else {
#pragma unroll
                for (int rr = 0; rr < 10; rr++)
                    v2[rr] = pack_f32x2(tl[ty * 6 + rr][2 * tx + dx + 2],
                                        tl[ty * 6 + rr][2 * tx + dx + 3]);
            }
#pragma unroll
            for (int c4 = 0; c4 < 4; c4++) {
                const float* wp = ws + (c4 * Ci + ci) * 25 + dx;
#pragma unroll
                for (int dy = 0; dy < 5; dy++) {
                    float wv = wp[dy * 5];
                    unsigned long long w2 = pack_f32x2(wv, wv);
#pragma unroll
                    for (int ry = 0; ry < 6; ry++) fma2(acc2[c4][ry], v2[ry + dy], w2);
                }
            }
        }
    }

    int xe = x0 + 2 * tx;
#pragma unroll
    for (int c4 = 0; c4 < 4; c4++) {
        float bv = bias[co0 + c4];
#pragma unroll
        for (int p = 0; p < 3; p++) {
            int y = y0 + ty * 6 + 2 * p;
            float a0, a1, b0, b1;
            unpack_f32x2(a0, a1, acc2[c4][2 * p]);
            unpack_f32x2(b0, b1, acc2[c4][2 * p + 1]);
            float r0 = fmaxf(gelu_f(a0 + bv), gelu_f(b0 + bv));
            float r1 = fmaxf(gelu_f(a1 + bv), gelu_f(b1 + bv));
            long long base = (((long long)b * Co + co0 + c4) * HP + (y >> 1)) * W;
            if (xe < W)     out[base + xe]     = r0;
            if (xe + 1 < W) out[base + xe + 1] = r1;
        }
    }
}

// ---------------- transpose [B,768,500] -> [B,500,768] ----------------
__global__ void transpose_kernel(const float* __restrict__ in, float* __restrict__ out)
{
    __shared__ float t[32][33];
    int b = blockIdx.z;
    int k0 = blockIdx.x * 32;
    int t0 = blockIdx.y * 32;
    int tx = threadIdx.x, ty = threadIdx.y;
    const float* ip = in + (long long)b * 768 * 500;
    float* op = out + (long long)b * 500 * 768;
#pragma unroll
    for (int r = 0; r < 32; r += 8) {
        int kk = k0 + ty + r, tt = t0 + tx;
        t[ty + r][tx] = (tt < 500) ? ip[(long long)kk * 500 + tt] : 0.f;
    }
    __syncthreads();
#pragma unroll
    for (int r = 0; r < 32; r += 8) {
        int tt = t0 + ty + r, kk = k0 + tx;
        if (tt < 500) op[(long long)tt * 768 + kk] = t[tx][ty + r];
    }
}

// ---------------- flash attention (fused QK^T + skew + softmax + PV) ------------
#define FA_QLD 132
#define FA_KLD 68
#define FA_PLD 68
#define FA_SMEM_FLOATS (64*FA_QLD + 64*FA_KLD + 64*FA_KLD + 128*FA_PLD)

extern __shared__ float fa_smem[];

__global__ void __launch_bounds__(256) flash_attn_kernel(
    const float* __restrict__ Q, const float* __restrict__ K,
    const float* __restrict__ V, const float* __restrict__ qer,
    float* __restrict__ O, int ldin)
{
    float* Qs = fa_smem;
    float* Ks = Qs + 64 * FA_QLD;
    float* Vs = Ks + 64 * FA_KLD;
    float* Ps = Vs + 64 * FA_KLD;

    const float scale = 0.125f;
    int qt = blockIdx.x;
    int h = blockIdx.y, b = blockIdx.z;
    int q0 = qt * 128;
    const float* Qp = Q + (long long)b * 500 * ldin + h * 64;
    const float* Kp = K + (long long)b * 500 * ldin + h * 64;
    const float* Vp = V + (long long)b * 500 * ldin + h * 64;
    const float* qerp = qer + (long long)(h * 16 + b) * 250000;

    int tid = threadIdx.x;
    int tx = tid & 15, ty = tid >> 4;

#pragma unroll
    for (int i = 0; i < 8; i++) {
        int r = i * 16 + (tid >> 4);
        int d4 = (tid & 15) * 4;
        float4 v = make_float4(0.f, 0.f, 0.f, 0.f);
        if (q0 + r < 500) v = *(const float4*)(Qp + (long long)(q0 + r) * ldin + d4);
        Qs[(d4 + 0) * FA_QLD + r] = v.x;
        Qs[(d4 + 1) * FA_QLD + r] = v.y;
        Qs[(d4 + 2) * FA_QLD + r] = v.z;
        Qs[(d4 + 3) * FA_QLD + r] = v.w;
    }

    float m[8], l[8], o[8][4];
#pragma unroll
    for (int i = 0; i < 8; i++) {
        m[i] = -1e30f; l[i] = 0.f;
#pragma unroll
        for (int j = 0; j < 4; j++) o[i][j] = 0.f;
    }
    __syncthreads();

    for (int kt0 = 0; kt0 < 500; kt0 += 64) {
#pragma unroll
        for (int i = 0; i < 4; i++) {
            int r = i * 16 + (tid >> 4);
            int d4 = (tid & 15) * 4;
            float4 kv = make_float4(0.f, 0.f, 0.f, 0.f);
            float4 vv = make_float4(0.f, 0.f, 0.f, 0.f);
            if (kt0 + r < 500) {
                kv = *(const float4*)(Kp + (long long)(kt0 + r) * ldin + d4);
                vv = *(const float4*)(Vp + (long long)(kt0 + r) * ldin + d4);
            }
            Ks[(d4 + 0) * FA_KLD + r] = kv.x;
            Ks[(d4 + 1) * FA_KLD + r] = kv.y;
            Ks[(d4 + 2) * FA_KLD + r] = kv.z;
            Ks[(d4 + 3) * FA_KLD + r] = kv.w;
            *(float4*)(Vs + r * FA_KLD + d4) = vv;
        }
        __syncthreads();

        float S[8][4];
#pragma unroll
        for (int i = 0; i < 8; i++)
#pragma unroll
            for (int j = 0; j < 4; j++) S[i][j] = 0.f;
#pragma unroll
        for (int d = 0; d < 64; d++) {
            float a[8];
            *(float4*)&a[0] = *(const float4*)(Qs + d * FA_QLD + ty * 8);
            *(float4*)&a[4] = *(const float4*)(Qs + d * FA_QLD + ty * 8 + 4);
            float4 bb = *(const float4*)(Ks + d * FA_KLD + tx * 4);
#pragma unroll
            for (int i = 0; i < 8; i++) {
                S[i][0] += a[i] * bb.x; S[i][1] += a[i] * bb.y;
                S[i][2] += a[i] * bb.z; S[i][3] += a[i] * bb.w;
            }
        }
#pragma unroll
        for (int i = 0; i < 8; i++) {
            int q = q0 + ty * 8 + i;
#pragma unroll
            for (int j = 0; j < 4; j++) {
                int k = kt0 + tx * 4 + j;
                if (q < 500 && k < 500) {
                    float srel;
                    if (k <= q)          srel = qerp[(long long)q * 500 + 499 - q + k];
                    else if (k == q + 1) srel = 0.f;
                    else                 srel = qerp[(long long)(q + 1) * 500 + k - q - 2];
                    S[i][j] = S[i][j] * scale + srel;
                } else {
                    S[i][j] = -1e30f;
                }
            }
        }
#pragma unroll
        for (int i = 0; i < 8; i++) {
            float rmax = fmaxf(fmaxf(S[i][0], S[i][1]), fmaxf(S[i][2], S[i][3]));
#pragma unroll
            for (int off = 1; off < 16; off <<= 1)
                rmax = fmaxf(rmax, __shfl_xor_sync(0xffffffffu, rmax, off, 32));
            float mnew = fmaxf(m[i], rmax);
            float corr = __expf(m[i] - mnew);
            float rsum = 0.f;
#pragma unroll
            for (int j = 0; j < 4; j++) {
                S[i][j] = __expf(S[i][j] - mnew);
                rsum += S[i][j];
            }
#pragma unroll
            for (int off = 1; off < 16; off <<= 1)
                rsum += __shfl_xor_sync(0xffffffffu, rsum, off, 32);
            l[i] = l[i] * corr + rsum;
            m[i] = mnew;
#pragma unroll
            for (int j = 0; j < 4; j++) o[i][j] *= corr;
            *(float4*)(Ps + (long long)(ty * 8 + i) * FA_PLD + tx * 4) =
                make_float4(S[i][0], S[i][1], S[i][2], S[i][3]);
        }
        __syncthreads();

#pragma unroll
        for (int kk4 = 0; kk4 < 64; kk4 += 4) {
            float4 vr0 = *(const float4*)(Vs + (kk4 + 0) * FA_KLD + tx * 4);
            float4 vr1 = *(const float4*)(Vs + (kk4 + 1) * FA_KLD + tx * 4);
            float4 vr2 = *(const float4*)(Vs + (kk4 + 2) * FA_KLD + tx * 4);
            float4 vr3 = *(const float4*)(Vs + (kk4 + 3) * FA_KLD + tx * 4);
#pragma unroll
            for (int i = 0; i < 8; i++) {
                float4 p4 = *(const float4*)(Ps + (long long)(ty * 8 + i) * FA_PLD + kk4);
                o[i][0] += p4.x * vr0.x + p4.y * vr1.x + p4.z * vr2.x + p4.w * vr3.x;
                o[i][1] += p4.x * vr0.y + p4.y * vr1.y + p4.z * vr2.y + p4.w * vr3.y;
                o[i][2] += p4.x * vr0.z + p4.y * vr1.z + p4.z * vr2.z + p4.w * vr3.z;
                o[i][3] += p4.x * vr0.w + p4.y * vr1.w + p4.z * vr2.w + p4.w * vr3.w;
            }
        }
        __syncthreads();
    }

    float* Op = O + (long long)b * 500 * 768 + h * 64;
#pragma unroll
    for (int i = 0; i < 8; i++) {
        int q = q0 + ty * 8 + i;
        if (q < 500) {
            float inv = 1.0f / l[i];
            *(float4*)(Op + (long long)q * 768 + tx * 4) =
                make_float4(o[i][0] * inv, o[i][1] * inv, o[i][2] * inv, o[i][3] * inv);
        }
    }
}

// ---------------- layernorm (row = 768), warp-shuffle reductions ----------------
__global__ void __launch_bounds__(256) layernorm_kernel(
    const float* __restrict__ in, float* __restrict__ out,
    const float* __restrict__ g, const float* __restrict__ b)
{
    __shared__ float part[8];
    int row = blockIdx.x, tid = threadIdx.x;
    int wid = tid >> 5, lane = tid & 31;
    const float* xp = in + (long long)row * 768;
    float v0 = xp[tid], v1 = xp[tid + 256], v2 = xp[tid + 512];

    float s = v0 + v1 + v2;
#pragma unroll
    for (int off = 16; off > 0; off >>= 1) s += __shfl_xor_sync(0xffffffffu, s, off, 32);
    if (lane == 0) part[wid] = s;
    __syncthreads();
    float mean = (part[0] + part[1] + part[2] + part[3] +
                  part[4] + part[5] + part[6] + part[7]) * (1.0f / 768.0f);
    __syncthreads();

    float d0 = v0 - mean, d1 = v1 - mean, d2 = v2 - mean;
    float q = d0 * d0 + d1 * d1 + d2 * d2;
#pragma unroll
    for (int off = 16; off > 0; off >>= 1) q += __shfl_xor_sync(0xffffffffu, q, off, 32);
    if (lane == 0) part[wid] = q;
    __syncthreads();
    float var = (part[0] + part[1] + part[2] + part[3] +
                 part[4] + part[5] + part[6] + part[7]) * (1.0f / 768.0f);
    float rstd = rsqrtf(var + 1e-5f);

    float* op = out + (long long)row * 768;
    op[tid]       = d0 * rstd * g[tid]       + b[tid];
    op[tid + 256] = d1 * rstd * g[tid + 256] + b[tid + 256];
    op[tid + 512] = d2 * rstd * g[tid + 512] + b[tid + 512];
}

// ---------------- orchestration ----------------
static void tc(const float* A, const float* B, const float* bias, const float* add,
               float* C, int M, int N, int K, int lda, int ldb, int ldc, int act,
               int batch = 1, long long bAo = 0, long long bCo = 0)
{
    dim3 grid((N + 127) / 128, (M + 127) / 128, batch);
    mma_gemm_kernel<<<grid, 256, MM_SMEM_BYTES>>>(A, B, bias, add, C, M, N, K,
                                                  lda, ldb, ldc, act, bAo, bCo);
}

extern "C" void kernel_launch(void* const* d_in, const int* in_sizes, int n_in,
                              void* d_out, int out_size)
{
    (void)in_sizes; (void)n_in; (void)out_size;
    const float* spec    = (const float*)d_in[0];
    const float* cw1     = (const float*)d_in[1];
    const float* cb1     = (const float*)d_in[2];
    const float* cw2     = (const float*)d_in[3];
    const float* cb2     = (const float*)d_in[4];
    const float* cw3     = (const float*)d_in[5];
    const float* cb3     = (const float*)d_in[6];
    const float* cw4     = (const float*)d_in[7];
    const float* cb4     = (const float*)d_in[8];
    const float* proj_w  = (const float*)d_in[9];
    const float* proj_b  = (const float*)d_in[10];
    const float* ln1_g   = (const float*)d_in[11];
    const float* ln1_b   = (const float*)d_in[12];
    const float* wq      = (const float*)d_in[13];
    const float* bq      = (const float*)d_in[14];
    const float* wk      = (const float*)d_in[15];
    const float* bk      = (const float*)d_in[16];
    const float* wv      = (const float*)d_in[17];
    const float* bv      = (const float*)d_in[18];
    const float* wo      = (const float*)d_in[19];
    const float* bo      = (const float*)d_in[20];
    const float* er      = (const float*)d_in[21];
    const float* ln2_g   = (const float*)d_in[22];
    const float* ln2_b   = (const float*)d_in[23];
    const float* w1      = (const float*)d_in[24];
    const float* b1      = (const float*)d_in[25];
    const float* w2      = (const float*)d_in[26];
    const float* b2      = (const float*)d_in[27];
    const float* deprj_w = (const float*)d_in[28];
    const float* deprj_b = (const float*)d_in[29];
    float* outp = (float*)d_out;

    float *bufA, *bufB, *qer, *qkv, *wqkv, *bqkv, *ert, *zerob, *x, *xn, *o;
    cudaGetSymbolAddress((void**)&bufA,  g_bufA);
    cudaGetSymbolAddress((void**)&bufB,  g_bufB);
    cudaGetSymbolAddress((void**)&qer,   g_qer);
    cudaGetSymbolAddress((void**)&qkv,   g_qkv);
    cudaGetSymbolAddress((void**)&wqkv,  g_wqkv);
    cudaGetSymbolAddress((void**)&bqkv,  g_bqkv);
    cudaGetSymbolAddress((void**)&ert,   g_ert);
    cudaGetSymbolAddress((void**)&zerob, g_zero);
    cudaGetSymbolAddress((void**)&x,     g_x);
    cudaGetSymbolAddress((void**)&xn,    g_xn);
    cudaGetSymbolAddress((void**)&o,     g_o);
    float* hbuf = bufB;

    const int fa_smem_bytes = FA_SMEM_FLOATS * 4;
    cudaFuncSetAttribute(flash_attn_kernel,
                         cudaFuncAttributeMaxDynamicSharedMemorySize, fa_smem_bytes);
    cudaFuncSetAttribute(mma_gemm_kernel,
                         cudaFuncAttributeMaxDynamicSharedMemorySize, MM_SMEM_BYTES);

    dim3 cblk(32, 4);
    // --- CNN with fused GELU+maxpool (launches 0-3) ---
    conv5x5_gelu_pool<<<dim3(8, 8 * 8, 16), cblk>>>(spec, cw1, cb1, bufB, 1, 32, 192);
    conv5x5_gelu_pool<<<dim3(8, 4 * 16, 16), cblk>>>(bufB, cw2, cb2, bufA, 32, 64, 96);
    conv5x5_gelu_pool<<<dim3(8, 2 * 16, 16), cblk>>>(bufA, cw3, cb3, bufB, 64, 64, 48);
    conv5x5_gelu_pool<<<dim3(8, 1 * 16, 16), cblk>>>(bufB, cw4, cb4, bufA, 64, 64, 24);
    // launch 4
    transpose_kernel<<<dim3(24, 16, 16), dim3(32, 8)>>>(bufA, xn);

    // proj — launch 5: ncu (-s 5 -c 1) captures this GEMM
    tc(xn, proj_w, proj_b, 0, x, 8000, 768, 768, 768, 768, 768, 0);

    // --- one-time prep (moved after proj; needed only before the layer loop) ---
    concat_qkv<<<(3 * 768 * 2304 + 255) / 256, 256>>>(wq, wk, wv, bq, bk, bv, wqkv, bqkv);
    er_transpose_all<<<dim3(64, 3), 512>>>(er, ert);

    for (int i = 0; i < L_; i++) {
        layernorm_kernel<<<8000, 256>>>(x, xn, ln1_g + i * 768, ln1_b + i * 768);
        // fused QKV: [8000][2304]
        tc(xn, wqkv + (long long)i * 768 * 2304, bqkv + i * 2304, 0, qkv,
           8000, 2304, 768, 768, 2304, 2304, 0);
        // qer (head-major) = Q_h @ er^T, batched over 12 heads
        tc(qkv, ert + (long long)i * 32768, zerob, 0, qer, 8000, 500, 64, 2304, 512, 500, 0,
           12, 64LL, 4000000LL);
        // fused attention
        flash_attn_kernel<<<dim3(4, 12, 16), 256, fa_smem_bytes>>>(
            qkv, qkv + 768, qkv + 1536, qer, o, 2304);
        // x = x + o @ wo + bo
        tc(o, wo + (long long)i * 768 * 768, bo + i * 768, x, x, 8000, 768, 768, 768, 768, 768, 0);
        layernorm_kernel<<<8000, 256>>>(x, xn, ln2_g + i * 768, ln2_b + i * 768);
        // h = gelu(xn @ w1 + b1)
        tc(xn, w1 + (long long)i * 768 * 3072, b1 + i * 3072, 0, hbuf, 8000, 3072, 768,
           768, 3072, 3072, 1);
        // x = x + h @ w2 + b2
        tc(hbuf, w2 + (long long)i * 3072 * 768, b2 + i * 768, x, x, 8000, 768, 3072,
           3072, 768, 768, 0);
    }
    // final deproj
    tc(x, deprj_w, deprj_b, 0, outp, 8000, 192, 768, 768, 192, 192, 0);
}

// round 17
// speedup vs baseline: 1.0698x; 1.0022x over previous
#include <cuda_runtime.h>
#include <math.h>
#include <stdint.h>

#define Bb_ 16
#define T_ 500
#define D_ 768
#define FFN_ 3072
#define NH_ 12
#define DH_ 64
#define L_ 3

// ---------------- scratch (device globals; no allocation) ----------------
__device__ float g_bufA[49152000];   // conv ping
__device__ float g_bufB[24576000];   // conv pong / FFN hidden
__device__ float g_qer[48000000];    // qer buffer, head-major [h][b][q][r]
__device__ float g_qkv[18432000];    // fused QKV [8000][2304]
__device__ float g_wqkv[5308416];    // fused QKV weights [3][768][2304]
__device__ float g_bqkv[6912];       // fused QKV bias [3][2304]
__device__ float g_ert[98304];       // er transposed+scaled [3][64][512]
__device__ float g_zero[512];        // zero bias (device globals are zero-init)
__device__ float g_x[6144000];
__device__ float g_xn[6144000];
__device__ float g_o[6144000];

__device__ __forceinline__ float gelu_f(float x) {
    return 0.5f * x * (1.0f + erff(x * 0.7071067811865475f));
}

__device__ __forceinline__ uint32_t tf32_rn(float x) {
    uint32_t r; asm("cvt.rna.tf32.f32 %0, %1;" : "=r"(r) : "f"(x));
    return r;
}

__device__ __forceinline__ uint32_t smem_u32(const void* p) {
    uint32_t a;
    asm("{ .reg .u64 t; cvta.to.shared.u64 t, %1; cvt.u32.u64 %0, t; }" : "=r"(a) : "l"(p));
    return a;
}

// ---- packed f32x2 helpers (Blackwell FFMA2) ----
__device__ __forceinline__ unsigned long long pack_f32x2(float lo, float hi) {
    unsigned long long d;
    asm("mov.b64 %0, {%1, %2};" : "=l"(d) : "r"(__float_as_uint(lo)), "r"(__float_as_uint(hi)));
    return d;
}
__device__ __forceinline__ void unpack_f32x2(float& lo, float& hi, unsigned long long v) {
    uint32_t a, b;
    asm("mov.b64 {%0, %1}, %2;" : "=r"(a), "=r"(b) : "l"(v));
    lo = __uint_as_float(a); hi = __uint_as_float(b);
}
__device__ __forceinline__ void fma2(unsigned long long& d, unsigned long long a,
                                     unsigned long long b) {
    asm("fma.rn.f32x2 %0, %1, %2, %0;" : "+l"(d) : "l"(a), "l"(b));
}

// ---------------- tensor-core dense GEMM via mma.sync (tf32) ----------------
// CTA tile 128x128, K-step 32, double-buffered smem. 8 warps 4(m)x2(n).
// A staged [m][k] ld=36 (vector STS.128); B staged [k][n] ld=136.
#define ALD 136
#define AKLD 36
#define A_STG (128 * AKLD)
#define STAGE_FLOATS (A_STG + 32 * ALD)
#define MM_SMEM_BYTES (2 * STAGE_FLOATS * 4)

extern __shared__ float mm_smem[];

__global__ void __launch_bounds__(256) mma_gemm_kernel(
    const float* __restrict__ A, const float* __restrict__ Bm,
    const float* __restrict__ bias, const float* __restrict__ addsrc,
    float* __restrict__ C, int M, int N, int K,
    int lda, int ldb, int ldc, int act, long long bAo, long long bCo)
{
    A += (long long)blockIdx.z * bAo;
    C += (long long)blockIdx.z * bCo;

    int tid = threadIdx.x;
    int wid = tid >> 5, lane = tid & 31;
    int grp = lane >> 2, tig = lane & 3;
    int wm = wid & 3, wn = wid >> 2;
    int m0 = blockIdx.y * 128, n0 = blockIdx.x * 128;

    int am = tid >> 1;
    int akh = (tid & 1) * 16;
    int bkr = tid >> 4;
    int bn = (tid & 15) * 8;

    float acc[2][8][4];
#pragma unroll
    for (int i = 0; i < 2; i++)
#pragma unroll
        for (int j = 0; j < 8; j++)
#pragma unroll
            for (int r = 0; r < 4; r++) acc[i][j][r] = 0.f;

    float4 pa[4], pb[2][2];
    bool okn = (n0 + bn < N);

    auto stage = [&](float* Asb, float* Bsb) {
#pragma unroll
        for (int i = 0; i < 4; i++) {
            uint4 q;
            q.x = tf32_rn(pa[i].x); q.y = tf32_rn(pa[i].y);
            q.z = tf32_rn(pa[i].z); q.w = tf32_rn(pa[i].w);
            *(uint4*)&Asb[am * AKLD + akh + i * 4] = q;
        }
#pragma unroll
        for (int p = 0; p < 2; p++) {
            uint4 q0, q1;
            q0.x = tf32_rn(pb[p][0].x); q0.y = tf32_rn(pb[p][0].y);
            q0.z = tf32_rn(pb[p][0].z); q0.w = tf32_rn(pb[p][0].w);
            q1.x = tf32_rn(pb[p][1].x); q1.y = tf32_rn(pb[p][1].y);
            q1.z = tf32_rn(pb[p][1].z); q1.w = tf32_rn(pb[p][1].w);
            uint32_t* bsp = (uint32_t*)&Bsb[(bkr + p * 16) * ALD + bn];
            *(uint4*)(bsp) = q0;
            *(uint4*)(bsp + 4) = q1;
        }
    };

    {
        const float* Ap = (m0 + am < M) ? A + (long long)(m0 + am) * lda + akh : (const float*)0;
#pragma unroll
        for (int i = 0; i < 4; i++)
            pa[i] = Ap ? *(const float4*)(Ap + i * 4) : make_float4(0.f, 0.f, 0.f, 0.f);
#pragma unroll
        for (int p = 0; p < 2; p++) {
            const float* Bp = Bm + (long long)(bkr + p * 16) * ldb + n0 + bn;
            pb[p][0] = okn ? *(const float4*)(Bp)     : make_float4(0.f, 0.f, 0.f, 0.f);
            pb[p][1] = okn ? *(const float4*)(Bp + 4) : make_float4(0.f, 0.f, 0.f, 0.f);
        }
    }
    stage(mm_smem, mm_smem + A_STG);
    __syncthreads();

    int st = 0;
    for (int k0 = 0;; k0 += 32) {
        bool last = (k0 + 32 >= K);
        if (!last) {
            int kn = k0 + 32;
            const float* Ap = (m0 + am < M) ? A + (long long)(m0 + am) * lda + kn + akh : (const float*)0;
#pragma unroll
            for (int i = 0; i < 4; i++)
                pa[i] = Ap ? *(const float4*)(Ap + i * 4) : make_float4(0.f, 0.f, 0.f, 0.f);
#pragma unroll
            for (int p = 0; p < 2; p++) {
                const float* Bp = Bm + (long long)(kn + bkr + p * 16) * ldb + n0 + bn;
                pb[p][0] = okn ? *(const float4*)(Bp)     : make_float4(0.f, 0.f, 0.f, 0.f);
                pb[p][1] = okn ? *(const float4*)(Bp + 4) : make_float4(0.f, 0.f, 0.f, 0.f);
            }
        }

        {
            const float* Asb = mm_smem + st * STAGE_FLOATS;
            const float* Bsb = Asb + A_STG;
#pragma unroll
            for (int ks = 0; ks < 4; ks++) {
                int kb = ks * 8;
                uint32_t a[2][4], b[8][2];
                int mB = wm * 32;
#pragma unroll
                for (int mf = 0; mf < 2; mf++) {
                    int mb = mB + mf * 16 + grp;
                    a[mf][0] = *(const uint32_t*)&Asb[(mb)     * AKLD + kb + tig];
                    a[mf][1] = *(const uint32_t*)&Asb[(mb + 8) * AKLD + kb + tig];
                    a[mf][2] = *(const uint32_t*)&Asb[(mb)     * AKLD + kb + tig + 4];
                    a[mf][3] = *(const uint32_t*)&Asb[(mb + 8) * AKLD + kb + tig + 4];
                }
                int nB = wn * 64;
#pragma unroll
                for (int nf = 0; nf < 8; nf++) {
                    int nb = nB + nf * 8 + grp;
                    b[nf][0] = *(const uint32_t*)&Bsb[(kb + tig) * ALD + nb];
                    b[nf][1] = *(const uint32_t*)&Bsb[(kb + tig + 4) * ALD + nb];
                }
#pragma unroll
                for (int mf = 0; mf < 2; mf++)
#pragma unroll
                    for (int nf = 0; nf < 8; nf++) {
                        asm volatile(
                            "mma.sync.aligned.m16n8k8.row.col.f32.tf32.tf32.f32 "
                            "{%0,%1,%2,%3}, {%4,%5,%6,%7}, {%8,%9}, {%0,%1,%2,%3};"
                            : "+f"(acc[mf][nf][0]), "+f"(acc[mf][nf][1]),
                              "+f"(acc[mf][nf][2]), "+f"(acc[mf][nf][3])
                            : "r"(a[mf][0]), "r"(a[mf][1]), "r"(a[mf][2]), "r"(a[mf][3]),
                              "r"(b[nf][0]), "r"(b[nf][1]));
                    }
            }
        }
        if (last) break;

        stage(mm_smem + (st ^ 1) * STAGE_FLOATS,
              mm_smem + (st ^ 1) * STAGE_FLOATS + A_STG);
        __syncthreads();
        st ^= 1;
    }

#pragma unroll
    for (int mf = 0; mf < 2; mf++) {
#pragma unroll
        for (int r = 0; r < 2; r++) {
            int m = m0 + wm * 32 + mf * 16 + grp + r * 8;
            if (m >= M) continue;
            float* Cp = C + (long long)m * ldc;
            const float* addp = addsrc ? addsrc + (long long)m * ldc : (const float*)0;
#pragma unroll
            for (int nf = 0; nf < 8; nf++) {
                int n = n0 + wn * 64 + nf * 8 + tig * 2;
                if (n >= N) continue;
                float v0 = acc[mf][nf][r * 2 + 0] + bias[n];
                float v1 = acc[mf][nf][r * 2 + 1] + bias[n + 1];
                if (act) { v0 = gelu_f(v0); v1 = gelu_f(v1); }
                if (addp) { v0 += addp[n]; v1 += addp[n + 1]; }
                Cp[n] = v0; Cp[n + 1] = v1;
            }
        }
    }
}

// ---------------- one-time weight prep kernels ----------------
__global__ void concat_qkv(const float* __restrict__ wq, const float* __restrict__ wk,
                           const float* __restrict__ wv, const float* __restrict__ bq,
                           const float* __restrict__ bk, const float* __restrict__ bv,
                           float* __restrict__ wqkv, float* __restrict__ bqkv)
{
    long long idx = (long long)blockIdx.x * blockDim.x + threadIdx.x;
    const long long TOT = 3LL * 768 * 2304;
    if (idx < TOT) {
        int i = (int)(idx / (768 * 2304));
        int rem = (int)(idx % (768 * 2304));
        int k = rem / 2304, n = rem % 2304;
        int sel = n / 768, nn = n % 768;
        const float* src = sel == 0 ? wq : sel == 1 ? wk : wv;
        wqkv[idx] = src[(long long)i * 589824 + k * 768 + nn];
    }
    if (idx < 3 * 2304) {
        int i = (int)(idx / 2304);
        int n = (int)(idx % 2304);
        int sel = n / 768, nn = n % 768;
        const float* src = sel == 0 ? bq : sel == 1 ? bk : bv;
        bqkv[idx] = src[i * 768 + nn];
    }
}

// er [L][500][64] -> out [L][64][512]: out[l][d][r] = 0.125*er[l][r][d], zero-padded
__global__ void er_transpose_all(const float* __restrict__ er, float* __restrict__ out)
{
    int l = blockIdx.y;
    int d = blockIdx.x;
    int r = threadIdx.x;
    out[(l * 64 + d) * 512 + r] =
        (r < 500) ? 0.125f * er[(long long)l * 32000 + r * 64 + d] : 0.f;
}

// ---------------- conv 5x5 + GELU + freq-maxpool, f32x2, cp.async pipelined ------
#define CTLD 76

__global__ void __launch_bounds__(128, 5) conv5x5_gelu_pool(
    const float* __restrict__ in, const float* __restrict__ w,
    const float* __restrict__ bias, float* __restrict__ out,
    int Ci, int Co, int H)
{
    const int W = 500;
    __shared__ float tile[2][28][CTLD];
    __shared__ float ws[6400];
    int tx = threadIdx.x, ty = threadIdx.y;
    int tid = ty * 32 + tx;
    int hBlocks = H / 24;
    int x0 = blockIdx.x * 64;
    int y0 = (blockIdx.y % hBlocks) * 24;
    int co0 = (blockIdx.y / hBlocks) * 4;
    int b = blockIdx.z;
    int HP = H >> 1;

    int wtot = 4 * Ci * 25;
    const float* wbase = w + (long long)co0 * Ci * 25;
    for (int s = tid; s < wtot; s += 128) ws[s] = wbase[s];

    uint32_t tb0 = smem_u32(&tile[0][0][0]);
    uint32_t tb1 = smem_u32(&tile[1][0][0]);

    auto issue = [&](int ci, int buf) {
        const float* ip = in + ((long long)(b * Ci + ci)) * H * W;
        uint32_t tb = buf ? tb1 : tb0;
        for (int idx = tid; idx < 448; idx += 128) {
            int r = idx >> 4, cv = idx & 15;
            int gy = y0 + r - 2;
            int gx = x0 + cv * 4;
            int sb = 0;
            if (gy >= 0 && gy < H) {
                int rem = W - gx;
                sb = rem >= 4 ? 16 : (rem > 0 ? rem * 4 : 0);
            }
            const float* src = (sb > 0) ? ip + (long long)gy * W + gx : ip;
            uint32_t dst = tb + (uint32_t)(r * CTLD + 4 + cv * 4) * 4u;
            asm volatile("cp.async.ca.shared.global [%0], [%1], 16, %2;"
                         :: "r"(dst), "l"(src), "r"(sb));
        }
        if (tid < 112) {
            int r = tid >> 2, hc = tid & 3;
            int col = (hc < 2) ? (2 + hc) : (66 + hc);
            int gx = (hc < 2) ? (x0 - 2 + hc) : (x0 + 62 + hc);
            int gy = y0 + r - 2;
            int sb = (gy >= 0 && gy < H && gx >= 0 && gx < W) ? 4 : 0;
            const float* src = sb ? ip + (long long)gy * W + gx : ip;
            uint32_t dst = tb + (uint32_t)(r * CTLD + col) * 4u;
            asm volatile("cp.async.ca.shared.global [%0], [%1], 4, %2;"
                         :: "r"(dst), "l"(src), "r"(sb));
        }
        asm volatile("cp.async.commit_group;" ::: "memory");
    };

    unsigned long long acc2[4][6];
#pragma unroll
    for (int i = 0; i < 4; i++)
#pragma unroll
        for (int j = 0; j < 6; j++) acc2[i][j] = 0ull;

    issue(0, 0);

    for (int ci = 0; ci < Ci; ci++) {
        asm volatile("cp.async.wait_group 0;" ::: "memory");
        __syncthreads();
        if (ci + 1 < Ci) issue(ci + 1, (ci + 1) & 1);

        const float (*tl)[CTLD] = tile[ci & 1];
#pragma unroll
        for (int dx = 0; dx < 5; dx++) {
            unsigned long long v2[10];
            if ((dx & 1) == 0) {
#pragma unroll
                for (int rr = 0; rr < 10; rr++)
                    v2[rr] = *(const unsigned long long*)&tl[ty * 6 + rr][2 * tx + dx + 2];
            } else {
#pragma unroll
                for (int rr = 0; rr < 10; rr++)
                    v2[rr] = pack_f32x2(tl[ty * 6 + rr][2 * tx + dx + 2],
                                        tl[ty * 6 + rr][2 * tx + dx + 3]);
            }
#pragma unroll
            for (int c4 = 0; c4 < 4; c4++) {
                const float* wp = ws + (c4 * Ci + ci) * 25 + dx;
#pragma unroll
                for (int dy = 0; dy < 5; dy++) {
                    float wv = wp[dy * 5];
                    unsigned long long w2 = pack_f32x2(wv, wv);
#pragma unroll
                    for (int ry = 0; ry < 6; ry++) fma2(acc2[c4][ry], v2[ry + dy], w2);
                }
            }
        }
    }

    int xe = x0 + 2 * tx;
#pragma unroll
    for (int c4 = 0; c4 < 4; c4++) {
        float bv = bias[co0 + c4];
#pragma unroll
        for (int p = 0; p < 3; p++) {
            int y = y0 + ty * 6 + 2 * p;
            float a0, a1, b0, b1;
            unpack_f32x2(a0, a1, acc2[c4][2 * p]);
            unpack_f32x2(b0, b1, acc2[c4][2 * p + 1]);
            float r0 = fmaxf(gelu_f(a0 + bv), gelu_f(b0 + bv));
            float r1 = fmaxf(gelu_f(a1 + bv), gelu_f(b1 + bv));
            long long base = (((long long)b * Co + co0 + c4) * HP + (y >> 1)) * W;
            if (xe < W)     out[base + xe]     = r0;
            if (xe + 1 < W) out[base + xe + 1] = r1;
        }
    }
}

// ---------------- transpose [B,768,500] -> [B,500,768] ----------------
__global__ void transpose_kernel(const float* __restrict__ in, float* __restrict__ out)
{
    __shared__ float t[32][33];
    int b = blockIdx.z;
    int k0 = blockIdx.x * 32;
    int t0 = blockIdx.y * 32;
    int tx = threadIdx.x, ty = threadIdx.y;
    const float* ip = in + (long long)b * 768 * 500;
    float* op = out + (long long)b * 500 * 768;
#pragma unroll
    for (int r = 0; r < 32; r += 8) {
        int kk = k0 + ty + r, tt = t0 + tx;
        t[ty + r][tx] = (tt < 500) ? ip[(long long)kk * 500 + tt] : 0.f;
    }
    __syncthreads();
#pragma unroll
    for (int r = 0; r < 32; r += 8) {
        int tt = t0 + ty + r, kk = k0 + tx;
        if (tt < 500) op[(long long)tt * 768 + kk] = t[tx][ty + r];
    }
}

// ---------------- flash attention (fused QK^T + skew + softmax + PV) ------------
#define FA_QLD 132
#define FA_KLD 68
#define FA_PLD 68
#define FA_SMEM_FLOATS (64*FA_QLD + 64*FA_KLD + 64*FA_KLD + 128*FA_PLD)

extern __shared__ float fa_smem[];

__global__ void __launch_bounds__(256) flash_attn_kernel(
    const float* __restrict__ Q, const float* __restrict__ K,
    const float* __restrict__ V, const float* __restrict__ qer,
    float* __restrict__ O, int ldin)
{
    float* Qs = fa_smem;
    float* Ks = Qs + 64 * FA_QLD;
    float* Vs = Ks + 64 * FA_KLD;
    float* Ps = Vs + 64 * FA_KLD;

    const float scale = 0.125f;
    int qt = blockIdx.x;
    int h = blockIdx.y, b = blockIdx.z;
    int q0 = qt * 128;
    const float* Qp = Q + (long long)b * 500 * ldin + h * 64;
    const float* Kp = K + (long long)b * 500 * ldin + h * 64;
    const float* Vp = V + (long long)b * 500 * ldin + h * 64;
    const float* qerp = qer + (long long)(h * 16 + b) * 250000;

    int tid = threadIdx.x;
    int tx = tid & 15, ty = tid >> 4;

#pragma unroll
    for (int i = 0; i < 8; i++) {
        int r = i * 16 + (tid >> 4);
        int d4 = (tid & 15) * 4;
        float4 v = make_float4(0.f, 0.f, 0.f, 0.f);
        if (q0 + r < 500) v = *(const float4*)(Qp + (long long)(q0 + r) * ldin + d4);
        Qs[(d4 + 0) * FA_QLD + r] = v.x;
        Qs[(d4 + 1) * FA_QLD + r] = v.y;
        Qs[(d4 + 2) * FA_QLD + r] = v.z;
        Qs[(d4 + 3) * FA_QLD + r] = v.w;
    }

    float m[8], l[8], o[8][4];
#pragma unroll
    for (int i = 0; i < 8; i++) {
        m[i] = -1e30f; l[i] = 0.f;
#pragma unroll
        for (int j = 0; j < 4; j++) o[i][j] = 0.f;
    }
    __syncthreads();

    for (int kt0 = 0; kt0 < 500; kt0 += 64) {
#pragma unroll
        for (int i = 0; i < 4; i++) {
            int r = i * 16 + (tid >> 4);
            int d4 = (tid & 15) * 4;
            float4 kv = make_float4(0.f, 0.f, 0.f, 0.f);
            float4 vv = make_float4(0.f, 0.f, 0.f, 0.f);
            if (kt0 + r < 500) {
                kv = *(const float4*)(Kp + (long long)(kt0 + r) * ldin + d4);
                vv = *(const float4*)(Vp + (long long)(kt0 + r) * ldin + d4);
            }
            Ks[(d4 + 0) * FA_KLD + r] = kv.x;
            Ks[(d4 + 1) * FA_KLD + r] = kv.y;
            Ks[(d4 + 2) * FA_KLD + r] = kv.z;
            Ks[(d4 + 3) * FA_KLD + r] = kv.w;
            *(float4*)(Vs + r * FA_KLD + d4) = vv;
        }
        __syncthreads();

        float S[8][4];
#pragma unroll
        for (int i = 0; i < 8; i++)
#pragma unroll
            for (int j = 0; j < 4; j++) S[i][j] = 0.f;
#pragma unroll
        for (int d = 0; d < 64; d++) {
            float a[8];
            *(float4*)&a[0] = *(const float4*)(Qs + d * FA_QLD + ty * 8);
            *(float4*)&a[4] = *(const float4*)(Qs + d * FA_QLD + ty * 8 + 4);
            float4 bb = *(const float4*)(Ks + d * FA_KLD + tx * 4);
#pragma unroll
            for (int i = 0; i < 8; i++) {
                S[i][0] += a[i] * bb.x; S[i][1] += a[i] * bb.y;
                S[i][2] += a[i] * bb.z; S[i][3] += a[i] * bb.w;
            }
        }
#pragma unroll
        for (int i = 0; i < 8; i++) {
            int q = q0 + ty * 8 + i;
#pragma unroll
            for (int j = 0; j < 4; j++) {
                int k = kt0 + tx * 4 + j;
                if (q < 500 && k < 500) {
                    float srel;
                    if (k <= q)          srel = qerp[(long long)q * 500 + 499 - q + k];
                    else if (k == q + 1) srel = 0.f;
                    else                 srel = qerp[(long long)(q + 1) * 500 + k - q - 2];
                    S[i][j] = S[i][j] * scale + srel;
                } else {
                    S[i][j] = -1e30f;
                }
            }
        }
#pragma unroll
        for (int i = 0; i < 8; i++) {
            float rmax = fmaxf(fmaxf(S[i][0], S[i][1]), fmaxf(S[i][2], S[i][3]));
#pragma unroll
            for (int off = 1; off < 16; off <<= 1)
                rmax = fmaxf(rmax, __shfl_xor_sync(0xffffffffu, rmax, off, 32));
            float mnew = fmaxf(m[i], rmax);
            float corr = __expf(m[i] - mnew);
            float rsum = 0.f;
#pragma unroll
            for (int j = 0; j < 4; j++) {
                S[i][j] = __expf(S[i][j] - mnew);
                rsum += S[i][j];
            }
#pragma unroll
            for (int off = 1; off < 16; off <<= 1)
                rsum += __shfl_xor_sync(0xffffffffu, rsum, off, 32);
            l[i] = l[i] * corr + rsum;
            m[i] = mnew;
#pragma unroll
            for (int j = 0; j < 4; j++) o[i][j] *= corr;
            *(float4*)(Ps + (long long)(ty * 8 + i) * FA_PLD + tx * 4) =
                make_float4(S[i][0], S[i][1], S[i][2], S[i][3]);
        }
        __syncthreads();

#pragma unroll
        for (int kk4 = 0; kk4 < 64; kk4 += 4) {
            float4 vr0 = *(const float4*)(Vs + (kk4 + 0) * FA_KLD + tx * 4);
            float4 vr1 = *(const float4*)(Vs + (kk4 + 1) * FA_KLD + tx * 4);
            float4 vr2 = *(const float4*)(Vs + (kk4 + 2) * FA_KLD + tx * 4);
            float4 vr3 = *(const float4*)(Vs + (kk4 + 3) * FA_KLD + tx * 4);
#pragma unroll
            for (int i = 0; i < 8; i++) {
                float4 p4 = *(const float4*)(Ps + (long long)(ty * 8 + i) * FA_PLD + kk4);
                o[i][0] += p4.x * vr0.x + p4.y * vr1.x + p4.z * vr2.x + p4.w * vr3.x;
                o[i][1] += p4.x * vr0.y + p4.y * vr1.y + p4.z * vr2.y + p4.w * vr3.y;
                o[i][2] += p4.x * vr0.z + p4.y * vr1.z + p4.z * vr2.z + p4.w * vr3.z;
                o[i][3] += p4.x * vr0.w + p4.y * vr1.w + p4.z * vr2.w + p4.w * vr3.w;
            }
        }
        __syncthreads();
    }

    float* Op = O + (long long)b * 500 * 768 + h * 64;
#pragma unroll
    for (int i = 0; i < 8; i++) {
        int q = q0 + ty * 8 + i;
        if (q < 500) {
            float inv = 1.0f / l[i];
            *(float4*)(Op + (long long)q * 768 + tx * 4) =
                make_float4(o[i][0] * inv, o[i][1] * inv, o[i][2] * inv, o[i][3] * inv);
        }
    }
}

// ---------------- layernorm (row = 768), float4 + warp-shuffle ----------------
// 192 threads: each owns one float4 of the row.
__global__ void __launch_bounds__(192) layernorm_kernel(
    const float* __restrict__ in, float* __restrict__ out,
    const float* __restrict__ g, const float* __restrict__ b)
{
    __shared__ float part[6];
    int row = blockIdx.x, tid = threadIdx.x;
    int wid = tid >> 5, lane = tid & 31;
    const float* xp = in + (long long)row * 768;
    float4 v = *(const float4*)(xp + tid * 4);

    float s = v.x + v.y + v.z + v.w;
#pragma unroll
    for (int off = 16; off > 0; off >>= 1) s += __shfl_xor_sync(0xffffffffu, s, off, 32);
    if (lane == 0) part[wid] = s;
    __syncthreads();
    float mean = (part[0] + part[1] + part[2] + part[3] + part[4] + part[5]) * (1.0f / 768.0f);
    __syncthreads();

    float4 d = make_float4(v.x - mean, v.y - mean, v.z - mean, v.w - mean);
    float q = d.x * d.x + d.y * d.y + d.z * d.z + d.w * d.w;
#pragma unroll
    for (int off = 16; off > 0; off >>= 1) q += __shfl_xor_sync(0xffffffffu, q, off, 32);
    if (lane == 0) part[wid] = q;
    __syncthreads();
    float var = (part[0] + part[1] + part[2] + part[3] + part[4] + part[5]) * (1.0f / 768.0f);
    float rstd = rsqrtf(var + 1e-5f);

    float4 gv = *(const float4*)(g + tid * 4);
    float4 bv = *(const float4*)(b + tid * 4);
    float4 r;
    r.x = d.x * rstd * gv.x + bv.x;
    r.y = d.y * rstd * gv.y + bv.y;
    r.z = d.z * rstd * gv.z + bv.z;
    r.w = d.w * rstd * gv.w + bv.w;
    *(float4*)(out + (long long)row * 768 + tid * 4) = r;
}

// ---------------- orchestration ----------------
static void tc(const float* A, const float* B, const float* bias, const float* add,
               float* C, int M, int N, int K, int lda, int ldb, int ldc, int act,
               int batch = 1, long long bAo = 0, long long bCo = 0)
{
    dim3 grid((N + 127) / 128, (M + 127) / 128, batch);
    mma_gemm_kernel<<<grid, 256, MM_SMEM_BYTES>>>(A, B, bias, add, C, M, N, K,
                                                  lda, ldb, ldc, act, bAo, bCo);
}

extern "C" void kernel_launch(void* const* d_in, const int* in_sizes, int n_in,
                              void* d_out, int out_size)
{
    (void)in_sizes; (void)n_in; (void)out_size;
    const float* spec    = (const float*)d_in[0];
    const float* cw1     = (const float*)d_in[1];
    const float* cb1     = (const float*)d_in[2];
    const float* cw2     = (const float*)d_in[3];
    const float* cb2     = (const float*)d_in[4];
    const float* cw3     = (const float*)d_in[5];
    const float* cb3     = (const float*)d_in[6];
    const float* cw4     = (const float*)d_in[7];
    const float* cb4     = (const float*)d_in[8];
    const float* proj_w  = (const float*)d_in[9];
    const float* proj_b  = (const float*)d_in[10];
    const float* ln1_g   = (const float*)d_in[11];
    const float* ln1_b   = (const float*)d_in[12];
    const float* wq      = (const float*)d_in[13];
    const float* bq      = (const float*)d_in[14];
    const float* wk      = (const float*)d_in[15];
    const float* bk      = (const float*)d_in[16];
    const float* wv      = (const float*)d_in[17];
    const float* bv      = (const float*)d_in[18];
    const float* wo      = (const float*)d_in[19];
    const float* bo      = (const float*)d_in[20];
    const float* er      = (const float*)d_in[21];
    const float* ln2_g   = (const float*)d_in[22];
    const float* ln2_b   = (const float*)d_in[23];
    const float* w1      = (const float*)d_in[24];
    const float* b1      = (const float*)d_in[25];
    const float* w2      = (const float*)d_in[26];
    const float* b2      = (const float*)d_in[27];
    const float* deprj_w = (const float*)d_in[28];
    const float* deprj_b = (const float*)d_in[29];
    float* outp = (float*)d_out;

    float *bufA, *bufB, *qer, *qkv, *wqkv, *bqkv, *ert, *zerob, *x, *xn, *o;
    cudaGetSymbolAddress((void**)&bufA,  g_bufA);
    cudaGetSymbolAddress((void**)&bufB,  g_bufB);
    cudaGetSymbolAddress((void**)&qer,   g_qer);
    cudaGetSymbolAddress((void**)&qkv,   g_qkv);
    cudaGetSymbolAddress((void**)&wqkv,  g_wqkv);
    cudaGetSymbolAddress((void**)&bqkv,  g_bqkv);
    cudaGetSymbolAddress((void**)&ert,   g_ert);
    cudaGetSymbolAddress((void**)&zerob, g_zero);
    cudaGetSymbolAddress((void**)&x,     g_x);
    cudaGetSymbolAddress((void**)&xn,    g_xn);
    cudaGetSymbolAddress((void**)&o,     g_o);
    float* hbuf = bufB;

    const int fa_smem_bytes = FA_SMEM_FLOATS * 4;
    cudaFuncSetAttribute(flash_attn_kernel,
                         cudaFuncAttributeMaxDynamicSharedMemorySize, fa_smem_bytes);
    cudaFuncSetAttribute(mma_gemm_kernel,
                         cudaFuncAttributeMaxDynamicSharedMemorySize, MM_SMEM_BYTES);

    dim3 cblk(32, 4);
    // --- CNN with fused GELU+maxpool (launches 0-3) ---
    conv5x5_gelu_pool<<<dim3(8, 8 * 8, 16), cblk>>>(spec, cw1, cb1, bufB, 1, 32, 192);
    conv5x5_gelu_pool<<<dim3(8, 4 * 16, 16), cblk>>>(bufB, cw2, cb2, bufA, 32, 64, 96);
    conv5x5_gelu_pool<<<dim3(8, 2 * 16, 16), cblk>>>(bufA, cw3, cb3, bufB, 64, 64, 48);
    conv5x5_gelu_pool<<<dim3(8, 1 * 16, 16), cblk>>>(bufB, cw4, cb4, bufA, 64, 64, 24);
    // launch 4
    transpose_kernel<<<dim3(24, 16, 16), dim3(32, 8)>>>(bufA, xn);

    // proj — launch 5
    tc(xn, proj_w, proj_b, 0, x, 8000, 768, 768, 768, 768, 768, 0);

    // --- one-time prep ---
    concat_qkv<<<(3 * 768 * 2304 + 255) / 256, 256>>>(wq, wk, wv, bq, bk, bv, wqkv, bqkv);
    er_transpose_all<<<dim3(64, 3), 512>>>(er, ert);

    for (int i = 0; i < L_; i++) {
        layernorm_kernel<<<8000, 192>>>(x, xn, ln1_g + i * 768, ln1_b + i * 768);
        // fused QKV: [8000][2304]
        tc(xn, wqkv + (long long)i * 768 * 2304, bqkv + i * 2304, 0, qkv,
           8000, 2304, 768, 768, 2304, 2304, 0);
        // qer (head-major) = Q_h @ er^T, batched over 12 heads
        tc(qkv, ert + (long long)i * 32768, zerob, 0, qer, 8000, 500, 64, 2304, 512, 500, 0,
           12, 64LL, 4000000LL);
        // fused attention
        flash_attn_kernel<<<dim3(4, 12, 16), 256, fa_smem_bytes>>>(
            qkv, qkv + 768, qkv + 1536, qer, o, 2304);
        // x = x + o @ wo + bo
        tc(o, wo + (long long)i * 768 * 768, bo + i * 768, x, x, 8000, 768, 768, 768, 768, 768, 0);
        layernorm_kernel<<<8000, 192>>>(x, xn, ln2_g + i * 768, ln2_b + i * 768);
        // h = gelu(xn @ w1 + b1)
        tc(xn, w1 + (long long)i * 768 * 3072, b1 + i * 3072, 0, hbuf, 8000, 3072, 768,
           768, 3072, 3072, 1);
        // x = x + h @ w2 + b2
        tc(hbuf, w2 + (long long)i * 3072 * 768, b2 + i * 768, x, x, 8000, 768, 3072,
           3072, 768, 768, 0);
    }
    // final deproj
    tc(x, deprj_w, deprj_b, 0, outp, 8000, 192, 768, 768, 192, 192, 0);
}